// round 5
// baseline (speedup 1.0000x reference)
#include <cuda_runtime.h>
#include <math.h>
#include <stdint.h>

#define NN 50000
#define EE 600000
#define HH 128
#define SCANB 98   // ceil(50000/512)

// ---------------- static device scratch (no allocs allowed) ----------------
__device__ float g_h[NN * HH];      // current node features
__device__ float g_hw[NN * HH];     // h @ W
__device__ float g_as[NN * 8];      // alpha_src per node/head
__device__ float g_ad[NN * 8];      // alpha_dst per node/head
__device__ int   g_cnt[NN];
__device__ int   g_rowoff[NN + 1];
__device__ int   g_cursor[NN];
__device__ int   g_csr[EE];
__device__ int   g_flags[1 + SCANB];   // [0]=ticket, [1+b]=flag (memset to 0 each launch)
__device__ int   g_aggv[SCANB];
__device__ int   g_prefv[SCANB];

// ---------------- tf32 helpers ----------------------------------------------
__device__ __forceinline__ uint32_t f2tf32(float v) {
    uint32_t t;
    asm("cvt.rna.tf32.f32 %0, %1;" : "=r"(t) : "f"(v));
    return t;
}
__device__ __forceinline__ void mma_tf32(float& c0, float& c1, float& c2, float& c3,
                                         uint32_t a0, uint32_t a1, uint32_t a2, uint32_t a3,
                                         uint32_t b0, uint32_t b1) {
    asm volatile(
        "mma.sync.aligned.m16n8k8.row.col.f32.tf32.tf32.f32 "
        "{%0,%1,%2,%3}, {%4,%5,%6,%7}, {%8,%9}, {%0,%1,%2,%3};"
        : "+f"(c0), "+f"(c1), "+f"(c2), "+f"(c3)
        : "r"(a0), "r"(a1), "r"(a2), "r"(a3), "r"(b0), "r"(b1));
}

// ---------------- HMMA tf32 GEMM (same structure as R4) ---------------------
template <int MODE>
__global__ void __launch_bounds__(256) mma_gemm(
    const float* __restrict__ A, const float* __restrict__ W, int ncols,
    const float* __restrict__ aux0, const float* __restrict__ aux1,
    float* __restrict__ C, int nrows) {
    extern __shared__ float sm[];
    float* As = sm;              // [8 mtile][16 kstep][128] = 16384 floats
    float* Bs = sm + 16384;      // [8 ntile][16 kstep][64]  = 8192 floats
    int tid = threadIdx.x;
    int row0 = blockIdx.x * 128;
    int colbase = blockIdx.y * 64;

    for (int i = tid; i < 128 * 128; i += 256) {
        int r = i >> 7, c = i & 127;
        int gr = row0 + r; if (gr >= nrows) gr = nrows - 1;
        uint32_t tv = f2tf32(A[(size_t)gr * 128 + c]);
        int mt = r >> 4, rr = r & 15, ks = c >> 3;
        int ln = ((rr & 7) << 2) | (c & 3);
        int rg = (rr >> 3) | (((c >> 2) & 1) << 1);
        As[((mt * 16 + ks) << 7) + (ln << 2) + rg] = __uint_as_float(tv);
    }
    for (int i = tid; i < 128 * 64; i += 256) {
        int k = i >> 6, n = i & 63;
        uint32_t tv = f2tf32(W[(size_t)k * ncols + colbase + n]);
        int nt = n >> 3, nn = n & 7, ks = k >> 3;
        int ln = (nn << 2) | (k & 3);
        int rg = (k >> 2) & 1;
        Bs[((nt * 16 + ks) << 6) + (ln << 1) + rg] = __uint_as_float(tv);
    }
    __syncthreads();

    int w = tid >> 5, lane = tid & 31;
    int wm = w >> 1, wn = w & 1;
    float acc[2][4][4];
#pragma unroll
    for (int mi = 0; mi < 2; mi++)
#pragma unroll
        for (int ni = 0; ni < 4; ni++)
#pragma unroll
            for (int j = 0; j < 4; j++) acc[mi][ni][j] = 0.f;

#pragma unroll
    for (int ks = 0; ks < 16; ks++) {
        uint32_t af[2][4];
#pragma unroll
        for (int mi = 0; mi < 2; mi++) {
            float4 v = *reinterpret_cast<const float4*>(
                &As[(((wm * 2 + mi) * 16 + ks) << 7) + (lane << 2)]);
            af[mi][0] = __float_as_uint(v.x); af[mi][1] = __float_as_uint(v.y);
            af[mi][2] = __float_as_uint(v.z); af[mi][3] = __float_as_uint(v.w);
        }
        uint32_t bf[4][2];
#pragma unroll
        for (int ni = 0; ni < 4; ni++) {
            float2 v = *reinterpret_cast<const float2*>(
                &Bs[(((wn * 4 + ni) * 16 + ks) << 6) + (lane << 1)]);
            bf[ni][0] = __float_as_uint(v.x); bf[ni][1] = __float_as_uint(v.y);
        }
#pragma unroll
        for (int mi = 0; mi < 2; mi++)
#pragma unroll
            for (int ni = 0; ni < 4; ni++)
                mma_tf32(acc[mi][ni][0], acc[mi][ni][1], acc[mi][ni][2], acc[mi][ni][3],
                         af[mi][0], af[mi][1], af[mi][2], af[mi][3],
                         bf[ni][0], bf[ni][1]);
    }

    int grp = lane >> 2, qd = lane & 3;
    float asr[2][2][2], adr[2][2][2];
    if (MODE == 0) {
#pragma unroll
        for (int mi = 0; mi < 2; mi++)
#pragma unroll
            for (int rh = 0; rh < 2; rh++)
#pragma unroll
                for (int hp = 0; hp < 2; hp++) { asr[mi][rh][hp] = 0.f; adr[mi][rh][hp] = 0.f; }
    }

#pragma unroll
    for (int mi = 0; mi < 2; mi++) {
#pragma unroll
        for (int ni = 0; ni < 4; ni++) {
            int cb = colbase + wn * 32 + ni * 8 + (qd << 1);
            int r = row0 + wm * 32 + mi * 16 + grp;
            float v0 = acc[mi][ni][0], v1 = acc[mi][ni][1];
            float v2 = acc[mi][ni][2], v3 = acc[mi][ni][3];
            if (MODE == 1) {
                float b0 = aux0[cb], b1 = aux0[cb + 1];
                v0 = fmaxf(v0 + b0, 0.f); v1 = fmaxf(v1 + b1, 0.f);
                v2 = fmaxf(v2 + b0, 0.f); v3 = fmaxf(v3 + b1, 0.f);
            }
            if (MODE == 0) {
                int hp = ni >> 1;
                float a0 = aux0[cb], a1 = aux0[cb + 1];
                float d0 = aux1[cb], d1 = aux1[cb + 1];
                asr[mi][0][hp] += v0 * a0 + v1 * a1;
                asr[mi][1][hp] += v2 * a0 + v3 * a1;
                adr[mi][0][hp] += v0 * d0 + v1 * d1;
                adr[mi][1][hp] += v2 * d0 + v3 * d1;
            }
            if (r < nrows)
                *reinterpret_cast<float2*>(&C[(size_t)r * ncols + cb]) = make_float2(v0, v1);
            if (r + 8 < nrows)
                *reinterpret_cast<float2*>(&C[(size_t)(r + 8) * ncols + cb]) = make_float2(v2, v3);
        }
    }

    if (MODE == 0) {
#pragma unroll
        for (int mi = 0; mi < 2; mi++)
#pragma unroll
            for (int rh = 0; rh < 2; rh++)
#pragma unroll
                for (int hp = 0; hp < 2; hp++) {
                    float a = asr[mi][rh][hp], d = adr[mi][rh][hp];
                    a += __shfl_xor_sync(0xffffffffu, a, 1);
                    a += __shfl_xor_sync(0xffffffffu, a, 2);
                    d += __shfl_xor_sync(0xffffffffu, d, 1);
                    d += __shfl_xor_sync(0xffffffffu, d, 2);
                    asr[mi][rh][hp] = a; adr[mi][rh][hp] = d;
                }
        if (qd == 0) {
            int h0 = (colbase + wn * 32) >> 4;
#pragma unroll
            for (int mi = 0; mi < 2; mi++)
#pragma unroll
                for (int rh = 0; rh < 2; rh++) {
                    int r = row0 + wm * 32 + mi * 16 + grp + rh * 8;
                    if (r < nrows) {
#pragma unroll
                        for (int hp = 0; hp < 2; hp++) {
                            g_as[r * 8 + h0 + hp] = asr[mi][rh][hp];
                            g_ad[r * 8 + h0 + hp] = adr[mi][rh][hp];
                        }
                    }
                }
        }
    }
}

// ---------------- fused input projection + degree count ---------------------
__global__ void proj_count(const float* __restrict__ x,
                           const float* __restrict__ W_in,
                           const float* __restrict__ b_in,
                           const int* __restrict__ dst) {
    int idx = blockIdx.x * blockDim.x + threadIdx.x;
    if (idx < NN * HH) {
        int n = idx >> 7, j = idx & 127;
        g_h[idx] = x[n * 2] * W_in[j] + x[n * 2 + 1] * W_in[128 + j] + b_in[j];
    }
    if (idx < EE) atomicAdd(&g_cnt[dst[idx]], 1);
}

// ---------------- single-kernel decoupled-lookback scan ---------------------
__global__ void __launch_bounds__(512) scan_lb() {
    __shared__ int sm[512];
    __shared__ int sbid, sprefix;
    if (threadIdx.x == 0) sbid = atomicAdd(&g_flags[0], 1);
    __syncthreads();
    int bid = sbid;
    int i = bid * 512 + threadIdx.x;
    int v = (i < NN) ? g_cnt[i] : 0;
    sm[threadIdx.x] = v;
    __syncthreads();
    for (int off = 1; off < 512; off <<= 1) {
        int t = (threadIdx.x >= off) ? sm[threadIdx.x - off] : 0;
        __syncthreads();
        sm[threadIdx.x] += t;
        __syncthreads();
    }
    int incl = sm[threadIdx.x];
    int total = sm[511];
    volatile int* flags = g_flags + 1;
    volatile int* aggv = g_aggv;
    volatile int* prefv = g_prefv;
    if (threadIdx.x == 0) {
        if (bid == 0) {
            prefv[0] = total;
            __threadfence();
            flags[0] = 2;
            sprefix = 0;
        } else {
            aggv[bid] = total;
            __threadfence();
            flags[bid] = 1;
            int pref = 0;
            for (int j = bid - 1; j >= 0;) {
                int f;
                do { f = flags[j]; } while (f == 0);
                if (f == 2) { pref += prefv[j]; break; }
                pref += aggv[j]; j--;
            }
            sprefix = pref;
            prefv[bid] = pref + total;
            __threadfence();
            flags[bid] = 2;
        }
    }
    __syncthreads();
    int off = sprefix + incl - v;
    if (i < NN) { g_rowoff[i] = off; g_cursor[i] = off; }
    if (i == 0) g_rowoff[NN] = EE;
}

__global__ void scatter(const int* __restrict__ src, const int* __restrict__ dst) {
    int e = blockIdx.x * blockDim.x + threadIdx.x;
    if (e < EE) {
        int d = dst[e];
        int pos = atomicAdd(&g_cursor[d], 1);
        g_csr[pos] = src[e];
    }
}

__device__ __forceinline__ float lrelu(float t) { return t > 0.f ? t : 0.2f * t; }

// ---------------- single-sweep edge-parallel aggregate + bias+relu+res+LN ---
// warp per node: 8 edge-slots x 4 dim-lanes. lane sub = lane&3 owns dims
// [sub*32, sub*32+32) = heads 2*sub, 2*sub+1. Numerator and denominator
// accumulated in one CSR sweep (no-max softmax), scaled at the end.
__global__ void __launch_bounds__(256) aggregate_kernel(
    const float* __restrict__ gb, const float* __restrict__ lng,
    const float* __restrict__ lnb) {
    int n = (blockIdx.x * blockDim.x + threadIdx.x) >> 5;
    if (n >= NN) return;
    int lane = threadIdx.x & 31;
    int sub = lane & 3, slot = lane >> 2;
    int beg = g_rowoff[n], end = g_rowoff[n + 1];
    int h0 = sub * 2;
    int c0 = sub * 32;

    float2 adp = *reinterpret_cast<const float2*>(&g_ad[n * 8 + h0]);
    float acc[32];
#pragma unroll
    for (int j = 0; j < 32; j++) acc[j] = 0.f;
    float den0 = 0.f, den1 = 0.f;

    if (slot == 0) {  // self loop
        float2 sa = *reinterpret_cast<const float2*>(&g_as[n * 8 + h0]);
        float w0 = __expf(lrelu(sa.x + adp.x));
        float w1 = __expf(lrelu(sa.y + adp.y));
        den0 = w0; den1 = w1;
        const float4* hp = reinterpret_cast<const float4*>(&g_hw[(size_t)n * 128 + c0]);
#pragma unroll
        for (int q = 0; q < 8; q++) {
            float4 v = hp[q];
            float w = (q < 4) ? w0 : w1;
            acc[q * 4 + 0] = v.x * w; acc[q * 4 + 1] = v.y * w;
            acc[q * 4 + 2] = v.z * w; acc[q * 4 + 3] = v.w * w;
        }
    }
    for (int i = beg + slot; i < end; i += 8) {
        int s = g_csr[i];
        float2 sa = *reinterpret_cast<const float2*>(&g_as[s * 8 + h0]);
        float w0 = __expf(lrelu(sa.x + adp.x));
        float w1 = __expf(lrelu(sa.y + adp.y));
        den0 += w0; den1 += w1;
        const float4* hp = reinterpret_cast<const float4*>(&g_hw[(size_t)s * 128 + c0]);
#pragma unroll
        for (int q = 0; q < 8; q++) {
            float4 v = hp[q];
            float w = (q < 4) ? w0 : w1;
            acc[q * 4 + 0] = fmaf(v.x, w, acc[q * 4 + 0]);
            acc[q * 4 + 1] = fmaf(v.y, w, acc[q * 4 + 1]);
            acc[q * 4 + 2] = fmaf(v.z, w, acc[q * 4 + 2]);
            acc[q * 4 + 3] = fmaf(v.w, w, acc[q * 4 + 3]);
        }
    }
    // reduce across the 8 slots (lanes with equal sub)
#pragma unroll
    for (int off = 4; off < 32; off <<= 1) {
        den0 += __shfl_xor_sync(0xffffffffu, den0, off);
        den1 += __shfl_xor_sync(0xffffffffu, den1, off);
#pragma unroll
        for (int j = 0; j < 32; j++)
            acc[j] += __shfl_xor_sync(0xffffffffu, acc[j], off);
    }
    float iv0 = 1.0f / den0, iv1 = 1.0f / den1;

    // epilogue (all lanes compute; slot 0 stores): bias, relu, residual, LN
    float s1 = 0.f, s2 = 0.f;
#pragma unroll
    for (int q = 0; q < 8; q++) {
        float iv = (q < 4) ? iv0 : iv1;
        float4 b4 = *reinterpret_cast<const float4*>(&gb[c0 + q * 4]);
        float4 r4 = *reinterpret_cast<const float4*>(&g_h[(size_t)n * 128 + c0 + q * 4]);
        float v0 = fmaxf(acc[q * 4 + 0] * iv + b4.x, 0.f) + r4.x;
        float v1 = fmaxf(acc[q * 4 + 1] * iv + b4.y, 0.f) + r4.y;
        float v2 = fmaxf(acc[q * 4 + 2] * iv + b4.z, 0.f) + r4.z;
        float v3 = fmaxf(acc[q * 4 + 3] * iv + b4.w, 0.f) + r4.w;
        acc[q * 4 + 0] = v0; acc[q * 4 + 1] = v1;
        acc[q * 4 + 2] = v2; acc[q * 4 + 3] = v3;
        s1 += v0 + v1 + v2 + v3;
        s2 += v0 * v0 + v1 * v1 + v2 * v2 + v3 * v3;
    }
    s1 += __shfl_xor_sync(0xffffffffu, s1, 1);
    s1 += __shfl_xor_sync(0xffffffffu, s1, 2);
    s2 += __shfl_xor_sync(0xffffffffu, s2, 1);
    s2 += __shfl_xor_sync(0xffffffffu, s2, 2);
    float mu = s1 * (1.f / 128.f);
    float var = s2 * (1.f / 128.f) - mu * mu;
    float rstd = rsqrtf(fmaxf(var, 0.f) + 1e-5f);
    if (slot == 0) {
#pragma unroll
        for (int q = 0; q < 8; q++) {
            float4 g4 = *reinterpret_cast<const float4*>(&lng[c0 + q * 4]);
            float4 bb = *reinterpret_cast<const float4*>(&lnb[c0 + q * 4]);
            float4 o;
            o.x = (acc[q * 4 + 0] - mu) * rstd * g4.x + bb.x;
            o.y = (acc[q * 4 + 1] - mu) * rstd * g4.y + bb.y;
            o.z = (acc[q * 4 + 2] - mu) * rstd * g4.z + bb.z;
            o.w = (acc[q * 4 + 3] - mu) * rstd * g4.w + bb.w;
            *reinterpret_cast<float4*>(&g_h[(size_t)n * 128 + c0 + q * 4]) = o;
        }
    }
}

// ---------------- MLP head final: out = t2 @ W3 + b3 ------------------------
__global__ void head_kernel(const float* __restrict__ W3,
                            const float* __restrict__ b3,
                            float* __restrict__ out) {
    int w = (blockIdx.x * blockDim.x + threadIdx.x) >> 5;
    int lane = threadIdx.x & 31;
    if (w >= NN) return;
    float2 a = *reinterpret_cast<const float2*>(&g_h[(size_t)w * 64 + lane * 2]);
    float2 wv = *reinterpret_cast<const float2*>(&W3[lane * 2]);
    float s = a.x * wv.x + a.y * wv.y;
#pragma unroll
    for (int off = 16; off; off >>= 1) s += __shfl_xor_sync(0xffffffffu, s, off);
    if (lane == 0) out[w] = s + b3[0];
}

// ---------------- launch ----------------------------------------------------
extern "C" void kernel_launch(void* const* d_in, const int* in_sizes, int n_in,
                              void* d_out, int out_size) {
    const float* x = (const float*)d_in[0];
    const int* ei = (const int*)d_in[1];
    const int* src = ei;
    const int* dst = ei + EE;
    const float* W_in = (const float*)d_in[3];
    const float* b_in = (const float*)d_in[4];
    float* out = (float*)d_out;

    float *p_h = nullptr, *p_hw = nullptr;
    int *p_cnt = nullptr, *p_flags = nullptr;
    cudaGetSymbolAddress((void**)&p_h, g_h);
    cudaGetSymbolAddress((void**)&p_hw, g_hw);
    cudaGetSymbolAddress((void**)&p_cnt, g_cnt);
    cudaGetSymbolAddress((void**)&p_flags, g_flags);

    const int SMEM_GEMM = (16384 + 8192) * 4;  // 96 KB
    cudaFuncSetAttribute(mma_gemm<0>, cudaFuncAttributeMaxDynamicSharedMemorySize, SMEM_GEMM);
    cudaFuncSetAttribute(mma_gemm<1>, cudaFuncAttributeMaxDynamicSharedMemorySize, SMEM_GEMM);
    const int NCTA = (NN + 127) / 128;  // 391

    cudaMemsetAsync(p_cnt, 0, NN * sizeof(int));
    cudaMemsetAsync(p_flags, 0, (1 + SCANB) * sizeof(int));

    proj_count<<<(NN * HH + 255) / 256, 256>>>(x, W_in, b_in, dst);
    scan_lb<<<SCANB, 512>>>();
    scatter<<<(EE + 255) / 256, 256>>>(src, dst);

    for (int l = 0; l < 3; l++) {
        const float* W  = (const float*)d_in[5 + 6 * l];
        const float* as = (const float*)d_in[6 + 6 * l];
        const float* ad = (const float*)d_in[7 + 6 * l];
        const float* gb = (const float*)d_in[8 + 6 * l];
        const float* lg = (const float*)d_in[9 + 6 * l];
        const float* lb = (const float*)d_in[10 + 6 * l];
        mma_gemm<0><<<dim3(NCTA, 2), 256, SMEM_GEMM>>>(p_h, W, 128, as, ad, p_hw, NN);
        aggregate_kernel<<<(NN + 7) / 8, 256>>>(gb, lg, lb);
    }
    // MLP head
    mma_gemm<1><<<dim3(NCTA, 2), 256, SMEM_GEMM>>>(p_h, (const float*)d_in[23], 128,
                                                   (const float*)d_in[24], nullptr, p_hw, NN);
    mma_gemm<1><<<dim3(NCTA, 1), 256, SMEM_GEMM>>>(p_hw, (const float*)d_in[25], 64,
                                                   (const float*)d_in[26], nullptr, p_h, NN);
    head_kernel<<<(NN * 32 + 255) / 256, 256>>>((const float*)d_in[27],
                                                (const float*)d_in[28], out);
}

// round 6
// speedup vs baseline: 1.6925x; 1.6925x over previous
#include <cuda_runtime.h>
#include <math.h>
#include <stdint.h>

#define NN 50000
#define EE 600000
#define HH 128
#define SCANB 98   // ceil(50000/512)

// ---------------- static device scratch (no allocs allowed) ----------------
__device__ float g_h[NN * HH];      // current node features
__device__ float g_hw[NN * HH];     // h @ W
__device__ float g_as[NN * 8];      // alpha_src per node/head
__device__ float g_ad[NN * 8];      // alpha_dst per node/head
__device__ int   g_cnt[NN];
__device__ int   g_rowoff[NN + 1];
__device__ int   g_cursor[NN];
__device__ int   g_csr[EE];
__device__ int   g_flags[1 + SCANB];
__device__ int   g_aggv[SCANB];
__device__ int   g_prefv[SCANB];

// ---------------- tf32 helpers ----------------------------------------------
__device__ __forceinline__ uint32_t f2tf32(float v) {
    uint32_t t;
    asm("cvt.rna.tf32.f32 %0, %1;" : "=r"(t) : "f"(v));
    return t;
}
__device__ __forceinline__ void mma_tf32(float& c0, float& c1, float& c2, float& c3,
                                         uint32_t a0, uint32_t a1, uint32_t a2, uint32_t a3,
                                         uint32_t b0, uint32_t b1) {
    asm volatile(
        "mma.sync.aligned.m16n8k8.row.col.f32.tf32.tf32.f32 "
        "{%0,%1,%2,%3}, {%4,%5,%6,%7}, {%8,%9}, {%0,%1,%2,%3};"
        : "+f"(c0), "+f"(c1), "+f"(c2), "+f"(c3)
        : "r"(a0), "r"(a1), "r"(a2), "r"(a3), "r"(b0), "r"(b1));
}

// ---------------- HMMA tf32 GEMM: C[rows, ncols] = A[rows,128] @ W[128,ncols]
// CTA tile 128 x 64 (col tile = blockIdx.y). 8 warps: 4(m) x 2(n).
// B staged in 32KB static SMEM (fragment-major); A fragments loaded DIRECTLY
// from global (quad-contiguous 16B segments, L1-cached, reused by both n-warps).
// MODE 0: store C + fused per-head attention dots (aux0=a_src, aux1=a_dst)
// MODE 1: bias (aux0) + relu
template <int MODE>
__global__ void __launch_bounds__(256, 3) mma_gemm(
    const float* __restrict__ A, const float* __restrict__ W, int ncols,
    const float* __restrict__ aux0, const float* __restrict__ aux1,
    float* __restrict__ C, int nrows) {
    __shared__ float Bs[8192];   // [8 ntile][16 kstep][64]
    int tid = threadIdx.x;
    int row0 = blockIdx.x * 128;
    int colbase = blockIdx.y * 64;

    // stage W cols [colbase, colbase+64) -> fragment-major (tf32-rounded)
    for (int i = tid; i < 128 * 64; i += 256) {
        int k = i >> 6, n = i & 63;
        uint32_t tv = f2tf32(W[(size_t)k * ncols + colbase + n]);
        int nt = n >> 3, nn = n & 7, ks = k >> 3;
        int ln = (nn << 2) | (k & 3);
        int rg = (k >> 2) & 1;
        Bs[((nt * 16 + ks) << 6) + (ln << 1) + rg] = __uint_as_float(tv);
    }
    __syncthreads();

    int w = tid >> 5, lane = tid & 31;
    int wm = w >> 1, wn = w & 1;
    int grp = lane >> 2, qd = lane & 3;

    // per-mi row pointers (clamped)
    const float* pA[2][2];
#pragma unroll
    for (int mi = 0; mi < 2; mi++) {
        int rA = row0 + wm * 32 + mi * 16 + grp;
        int rB = rA + 8;
        if (rA >= nrows) rA = nrows - 1;
        if (rB >= nrows) rB = nrows - 1;
        pA[mi][0] = &A[(size_t)rA * 128];
        pA[mi][1] = &A[(size_t)rB * 128];
    }

    float acc[2][4][4];
#pragma unroll
    for (int mi = 0; mi < 2; mi++)
#pragma unroll
        for (int ni = 0; ni < 4; ni++)
#pragma unroll
            for (int j = 0; j < 4; j++) acc[mi][ni][j] = 0.f;

#pragma unroll
    for (int ks = 0; ks < 16; ks++) {
        uint32_t af[2][4];
#pragma unroll
        for (int mi = 0; mi < 2; mi++) {
            af[mi][0] = f2tf32(pA[mi][0][ks * 8 + qd]);
            af[mi][1] = f2tf32(pA[mi][1][ks * 8 + qd]);
            af[mi][2] = f2tf32(pA[mi][0][ks * 8 + qd + 4]);
            af[mi][3] = f2tf32(pA[mi][1][ks * 8 + qd + 4]);
        }
        uint32_t bf[4][2];
#pragma unroll
        for (int ni = 0; ni < 4; ni++) {
            float2 v = *reinterpret_cast<const float2*>(
                &Bs[(((wn * 4 + ni) * 16 + ks) << 6) + (lane << 1)]);
            bf[ni][0] = __float_as_uint(v.x); bf[ni][1] = __float_as_uint(v.y);
        }
#pragma unroll
        for (int mi = 0; mi < 2; mi++)
#pragma unroll
            for (int ni = 0; ni < 4; ni++)
                mma_tf32(acc[mi][ni][0], acc[mi][ni][1], acc[mi][ni][2], acc[mi][ni][3],
                         af[mi][0], af[mi][1], af[mi][2], af[mi][3],
                         bf[ni][0], bf[ni][1]);
    }

    float asr[2][2][2], adr[2][2][2];
    if (MODE == 0) {
#pragma unroll
        for (int mi = 0; mi < 2; mi++)
#pragma unroll
            for (int rh = 0; rh < 2; rh++)
#pragma unroll
                for (int hp = 0; hp < 2; hp++) { asr[mi][rh][hp] = 0.f; adr[mi][rh][hp] = 0.f; }
    }

#pragma unroll
    for (int mi = 0; mi < 2; mi++) {
#pragma unroll
        for (int ni = 0; ni < 4; ni++) {
            int cb = colbase + wn * 32 + ni * 8 + (qd << 1);
            int r = row0 + wm * 32 + mi * 16 + grp;
            float v0 = acc[mi][ni][0], v1 = acc[mi][ni][1];
            float v2 = acc[mi][ni][2], v3 = acc[mi][ni][3];
            if (MODE == 1) {
                float b0 = aux0[cb], b1 = aux0[cb + 1];
                v0 = fmaxf(v0 + b0, 0.f); v1 = fmaxf(v1 + b1, 0.f);
                v2 = fmaxf(v2 + b0, 0.f); v3 = fmaxf(v3 + b1, 0.f);
            }
            if (MODE == 0) {
                int hp = ni >> 1;
                float a0 = aux0[cb], a1 = aux0[cb + 1];
                float d0 = aux1[cb], d1 = aux1[cb + 1];
                asr[mi][0][hp] += v0 * a0 + v1 * a1;
                asr[mi][1][hp] += v2 * a0 + v3 * a1;
                adr[mi][0][hp] += v0 * d0 + v1 * d1;
                adr[mi][1][hp] += v2 * d0 + v3 * d1;
            }
            if (r < nrows)
                *reinterpret_cast<float2*>(&C[(size_t)r * ncols + cb]) = make_float2(v0, v1);
            if (r + 8 < nrows)
                *reinterpret_cast<float2*>(&C[(size_t)(r + 8) * ncols + cb]) = make_float2(v2, v3);
        }
    }

    if (MODE == 0) {
#pragma unroll
        for (int mi = 0; mi < 2; mi++)
#pragma unroll
            for (int rh = 0; rh < 2; rh++)
#pragma unroll
                for (int hp = 0; hp < 2; hp++) {
                    float a = asr[mi][rh][hp], d = adr[mi][rh][hp];
                    a += __shfl_xor_sync(0xffffffffu, a, 1);
                    a += __shfl_xor_sync(0xffffffffu, a, 2);
                    d += __shfl_xor_sync(0xffffffffu, d, 1);
                    d += __shfl_xor_sync(0xffffffffu, d, 2);
                    asr[mi][rh][hp] = a; adr[mi][rh][hp] = d;
                }
        if (qd == 0) {
            int h0 = (colbase + wn * 32) >> 4;
#pragma unroll
            for (int mi = 0; mi < 2; mi++)
#pragma unroll
                for (int rh = 0; rh < 2; rh++) {
                    int r = row0 + wm * 32 + mi * 16 + grp + rh * 8;
                    if (r < nrows) {
#pragma unroll
                        for (int hp = 0; hp < 2; hp++) {
                            g_as[r * 8 + h0 + hp] = asr[mi][rh][hp];
                            g_ad[r * 8 + h0 + hp] = adr[mi][rh][hp];
                        }
                    }
                }
        }
    }
}

// ---------------- fused input projection + degree count ---------------------
__global__ void proj_count(const float* __restrict__ x,
                           const float* __restrict__ W_in,
                           const float* __restrict__ b_in,
                           const int* __restrict__ dst) {
    int idx = blockIdx.x * blockDim.x + threadIdx.x;
    if (idx < NN * HH) {
        int n = idx >> 7, j = idx & 127;
        g_h[idx] = x[n * 2] * W_in[j] + x[n * 2 + 1] * W_in[128 + j] + b_in[j];
    }
    if (idx < EE) atomicAdd(&g_cnt[dst[idx]], 1);
}

// ---------------- single-kernel decoupled-lookback scan ---------------------
__global__ void __launch_bounds__(512) scan_lb() {
    __shared__ int sm[512];
    __shared__ int sbid, sprefix;
    if (threadIdx.x == 0) sbid = atomicAdd(&g_flags[0], 1);
    __syncthreads();
    int bid = sbid;
    int i = bid * 512 + threadIdx.x;
    int v = (i < NN) ? g_cnt[i] : 0;
    sm[threadIdx.x] = v;
    __syncthreads();
    for (int off = 1; off < 512; off <<= 1) {
        int t = (threadIdx.x >= off) ? sm[threadIdx.x - off] : 0;
        __syncthreads();
        sm[threadIdx.x] += t;
        __syncthreads();
    }
    int incl = sm[threadIdx.x];
    int total = sm[511];
    volatile int* flags = g_flags + 1;
    volatile int* aggv = g_aggv;
    volatile int* prefv = g_prefv;
    if (threadIdx.x == 0) {
        if (bid == 0) {
            prefv[0] = total;
            __threadfence();
            flags[0] = 2;
            sprefix = 0;
        } else {
            aggv[bid] = total;
            __threadfence();
            flags[bid] = 1;
            int pref = 0;
            for (int j = bid - 1; j >= 0;) {
                int f;
                do { f = flags[j]; } while (f == 0);
                if (f == 2) { pref += prefv[j]; break; }
                pref += aggv[j]; j--;
            }
            sprefix = pref;
            prefv[bid] = pref + total;
            __threadfence();
            flags[bid] = 2;
        }
    }
    __syncthreads();
    int off = sprefix + incl - v;
    if (i < NN) { g_rowoff[i] = off; g_cursor[i] = off; }
    if (i == 0) g_rowoff[NN] = EE;
}

__global__ void scatter(const int* __restrict__ src, const int* __restrict__ dst) {
    int e = blockIdx.x * blockDim.x + threadIdx.x;
    if (e < EE) {
        int d = dst[e];
        int pos = atomicAdd(&g_cursor[d], 1);
        g_csr[pos] = src[e];
    }
}

__device__ __forceinline__ float lrelu(float t) { return t > 0.f ? t : 0.2f * t; }

// ---------------- warp-per-node softmax aggregate (R4 two-pass, proven) ----
__global__ void __launch_bounds__(256) aggregate_kernel(
    const float* __restrict__ gb, const float* __restrict__ lng,
    const float* __restrict__ lnb) {
    int n = (blockIdx.x * blockDim.x + threadIdx.x) >> 5;
    if (n >= NN) return;
    int lane = threadIdx.x & 31;
    int beg = g_rowoff[n], end = g_rowoff[n + 1];

    float adl = (lane < 8) ? g_ad[n * 8 + lane] : 0.f;
    float asl = (lane < 8) ? g_as[n * 8 + lane] : 0.f;
    float adv[8], selfl[8];
#pragma unroll
    for (int hh = 0; hh < 8; hh++) {
        adv[hh] = __shfl_sync(0xffffffffu, adl, hh);
        float s = __shfl_sync(0xffffffffu, asl, hh);
        selfl[hh] = lrelu(s + adv[hh]);
    }
    // pass 1: denominator (self loop included on lane 0)
    float dsum[8];
#pragma unroll
    for (int hh = 0; hh < 8; hh++)
        dsum[hh] = (lane == 0) ? __expf(selfl[hh]) : 0.f;
    for (int i = beg + lane; i < end; i += 32) {
        int s = g_csr[i];
#pragma unroll
        for (int hh = 0; hh < 8; hh++)
            dsum[hh] += __expf(lrelu(g_as[s * 8 + hh] + adv[hh]));
    }
#pragma unroll
    for (int hh = 0; hh < 8; hh++)
#pragma unroll
        for (int off = 16; off; off >>= 1)
            dsum[hh] += __shfl_xor_sync(0xffffffffu, dsum[hh], off);
    float invd[8];
#pragma unroll
    for (int hh = 0; hh < 8; hh++) invd[hh] = 1.0f / dsum[hh];

    // pass 2: weighted aggregation; lane owns dims [4*lane,4*lane+4)
    int c0 = lane * 4;
    int mh = lane >> 2;
    float iv = 0.f, sl = 0.f;
#pragma unroll
    for (int hh = 0; hh < 8; hh++)
        if (mh == hh) { iv = invd[hh]; sl = selfl[hh]; }
    float admh = __shfl_sync(0xffffffffu, adl, mh);

    float a0, a1, a2, a3;
    {
        float wgt = __expf(sl) * iv;  // self loop
        float4 v = *reinterpret_cast<const float4*>(&g_hw[(size_t)n * 128 + c0]);
        a0 = v.x * wgt; a1 = v.y * wgt; a2 = v.z * wgt; a3 = v.w * wgt;
    }
    for (int i = beg; i < end; i++) {
        int s = g_csr[i];
        float t = lrelu(g_as[s * 8 + mh] + admh);
        float wgt = __expf(t) * iv;
        float4 v = *reinterpret_cast<const float4*>(&g_hw[(size_t)s * 128 + c0]);
        a0 = fmaf(v.x, wgt, a0);
        a1 = fmaf(v.y, wgt, a1);
        a2 = fmaf(v.z, wgt, a2);
        a3 = fmaf(v.w, wgt, a3);
    }
    // epilogue: + gat bias, relu, + residual, LayerNorm
    float4 b4 = *reinterpret_cast<const float4*>(&gb[c0]);
    float v0 = fmaxf(a0 + b4.x, 0.f), v1 = fmaxf(a1 + b4.y, 0.f);
    float v2 = fmaxf(a2 + b4.z, 0.f), v3 = fmaxf(a3 + b4.w, 0.f);
    float4 r4 = *reinterpret_cast<const float4*>(&g_h[(size_t)n * 128 + c0]);
    v0 += r4.x; v1 += r4.y; v2 += r4.z; v3 += r4.w;
    float s1 = v0 + v1 + v2 + v3;
    float s2 = v0 * v0 + v1 * v1 + v2 * v2 + v3 * v3;
#pragma unroll
    for (int off = 16; off; off >>= 1) {
        s1 += __shfl_xor_sync(0xffffffffu, s1, off);
        s2 += __shfl_xor_sync(0xffffffffu, s2, off);
    }
    float mu = s1 * (1.f / 128.f);
    float var = s2 * (1.f / 128.f) - mu * mu;
    float rstd = rsqrtf(fmaxf(var, 0.f) + 1e-5f);
    float4 g4 = *reinterpret_cast<const float4*>(&lng[c0]);
    float4 bb4 = *reinterpret_cast<const float4*>(&lnb[c0]);
    float4 o;
    o.x = (v0 - mu) * rstd * g4.x + bb4.x;
    o.y = (v1 - mu) * rstd * g4.y + bb4.y;
    o.z = (v2 - mu) * rstd * g4.z + bb4.z;
    o.w = (v3 - mu) * rstd * g4.w + bb4.w;
    *reinterpret_cast<float4*>(&g_h[(size_t)n * 128 + c0]) = o;
}

// ---------------- MLP head final: out = t2 @ W3 + b3 ------------------------
__global__ void head_kernel(const float* __restrict__ W3,
                            const float* __restrict__ b3,
                            float* __restrict__ out) {
    int w = (blockIdx.x * blockDim.x + threadIdx.x) >> 5;
    int lane = threadIdx.x & 31;
    if (w >= NN) return;
    float2 a = *reinterpret_cast<const float2*>(&g_h[(size_t)w * 64 + lane * 2]);
    float2 wv = *reinterpret_cast<const float2*>(&W3[lane * 2]);
    float s = a.x * wv.x + a.y * wv.y;
#pragma unroll
    for (int off = 16; off; off >>= 1) s += __shfl_xor_sync(0xffffffffu, s, off);
    if (lane == 0) out[w] = s + b3[0];
}

// ---------------- launch ----------------------------------------------------
extern "C" void kernel_launch(void* const* d_in, const int* in_sizes, int n_in,
                              void* d_out, int out_size) {
    const float* x = (const float*)d_in[0];
    const int* ei = (const int*)d_in[1];
    const int* src = ei;
    const int* dst = ei + EE;
    const float* W_in = (const float*)d_in[3];
    const float* b_in = (const float*)d_in[4];
    float* out = (float*)d_out;

    float *p_h = nullptr, *p_hw = nullptr;
    int *p_cnt = nullptr, *p_flags = nullptr;
    cudaGetSymbolAddress((void**)&p_h, g_h);
    cudaGetSymbolAddress((void**)&p_hw, g_hw);
    cudaGetSymbolAddress((void**)&p_cnt, g_cnt);
    cudaGetSymbolAddress((void**)&p_flags, g_flags);

    const int NCTA = (NN + 127) / 128;  // 391

    cudaMemsetAsync(p_cnt, 0, NN * sizeof(int));
    cudaMemsetAsync(p_flags, 0, (1 + SCANB) * sizeof(int));

    proj_count<<<(NN * HH + 255) / 256, 256>>>(x, W_in, b_in, dst);
    scan_lb<<<SCANB, 512>>>();
    scatter<<<(EE + 255) / 256, 256>>>(src, dst);

    for (int l = 0; l < 3; l++) {
        const float* W  = (const float*)d_in[5 + 6 * l];
        const float* as = (const float*)d_in[6 + 6 * l];
        const float* ad = (const float*)d_in[7 + 6 * l];
        const float* gb = (const float*)d_in[8 + 6 * l];
        const float* lg = (const float*)d_in[9 + 6 * l];
        const float* lb = (const float*)d_in[10 + 6 * l];
        mma_gemm<0><<<dim3(NCTA, 2), 256>>>(p_h, W, 128, as, ad, p_hw, NN);
        aggregate_kernel<<<(NN + 7) / 8, 256>>>(gb, lg, lb);
    }
    // MLP head
    mma_gemm<1><<<dim3(NCTA, 2), 256>>>(p_h, (const float*)d_in[23], 128,
                                        (const float*)d_in[24], nullptr, p_hw, NN);
    mma_gemm<1><<<dim3(NCTA, 1), 256>>>(p_hw, (const float*)d_in[25], 64,
                                        (const float*)d_in[26], nullptr, p_h, NN);
    head_kernel<<<(NN * 32 + 255) / 256, 256>>>((const float*)d_in[27],
                                                (const float*)d_in[28], out);
}

// round 7
// speedup vs baseline: 1.7793x; 1.0513x over previous
#include <cuda_runtime.h>
#include <math.h>
#include <stdint.h>

#define NN 50000
#define EE 600000
#define HH 128

// ---------------- static device scratch (no allocs allowed) ----------------
__device__ float g_h[NN * HH];      // current node features
__device__ float g_hw[NN * HH];     // h @ W
__device__ float g_as[NN * 8];      // alpha_src per node/head
__device__ float g_ad[NN * 8];      // alpha_dst per node/head
__device__ int   g_cnt[NN];
__device__ int   g_incl[NN];
__device__ int   g_rowoff[NN + 1];
__device__ int   g_cursor[NN];
__device__ int   g_bsum[128];
__device__ int   g_bofs[128];
__device__ int   g_csr[EE];

// ---------------- tf32 helpers ----------------------------------------------
__device__ __forceinline__ uint32_t f2tf32(float v) {
    uint32_t t;
    asm("cvt.rna.tf32.f32 %0, %1;" : "=r"(t) : "f"(v));
    return t;
}
__device__ __forceinline__ void mma_tf32(float& c0, float& c1, float& c2, float& c3,
                                         uint32_t a0, uint32_t a1, uint32_t a2, uint32_t a3,
                                         uint32_t b0, uint32_t b1) {
    asm volatile(
        "mma.sync.aligned.m16n8k8.row.col.f32.tf32.tf32.f32 "
        "{%0,%1,%2,%3}, {%4,%5,%6,%7}, {%8,%9}, {%0,%1,%2,%3};"
        : "+f"(c0), "+f"(c1), "+f"(c2), "+f"(c3)
        : "r"(a0), "r"(a1), "r"(a2), "r"(a3), "r"(b0), "r"(b1));
}

// ---------------- HMMA tf32 GEMM: C[rows, ncols] = A[rows,128] @ W[128,ncols]
// CTA tile: 128 rows x 64 cols (col tile = blockIdx.y), 512 threads.
// 16 warps: 8 (m, 16 rows each) x 2 (n, 32 cols each); 1 mi x 4 ni per warp.
// SMEM: A 64KB + B 32KB = 96KB, 2 CTAs/SM -> 32 warps resident.
// MODE 0: store C + fused per-head attention dots (aux0=a_src, aux1=a_dst)
// MODE 1: bias (aux0) + relu
template <int MODE>
__global__ void __launch_bounds__(512, 2) mma_gemm(
    const float* __restrict__ A, const float* __restrict__ W, int ncols,
    const float* __restrict__ aux0, const float* __restrict__ aux1,
    float* __restrict__ C, int nrows) {
    extern __shared__ float sm[];
    float* As = sm;              // [8 mtile(16r)][16 kstep][128] = 16384 floats
    float* Bs = sm + 16384;      // [8 ntile][16 kstep][64]       = 8192 floats
    int tid = threadIdx.x;
    int row0 = blockIdx.x * 128;
    int colbase = blockIdx.y * 64;

    // stage A -> fragment-major (tf32-rounded); coalesced float4 global reads
    for (int i = tid; i < 128 * 128; i += 512) {
        int r = i >> 7, c = i & 127;
        int gr = row0 + r; if (gr >= nrows) gr = nrows - 1;
        uint32_t tv = f2tf32(A[(size_t)gr * 128 + c]);
        int mt = r >> 4, rr = r & 15, ks = c >> 3;
        int ln = ((rr & 7) << 2) | (c & 3);
        int rg = (rr >> 3) | (((c >> 2) & 1) << 1);
        As[((mt * 16 + ks) << 7) + (ln << 2) + rg] = __uint_as_float(tv);
    }
    // stage W cols [colbase, colbase+64) -> fragment-major
    for (int i = tid; i < 128 * 64; i += 512) {
        int k = i >> 6, n = i & 63;
        uint32_t tv = f2tf32(W[(size_t)k * ncols + colbase + n]);
        int nt = n >> 3, nn = n & 7, ks = k >> 3;
        int ln = (nn << 2) | (k & 3);
        int rg = (k >> 2) & 1;
        Bs[((nt * 16 + ks) << 6) + (ln << 1) + rg] = __uint_as_float(tv);
    }
    __syncthreads();

    int w = tid >> 5, lane = tid & 31;
    int wm = w >> 1, wn = w & 1;
    float acc[4][4];
#pragma unroll
    for (int ni = 0; ni < 4; ni++)
#pragma unroll
        for (int j = 0; j < 4; j++) acc[ni][j] = 0.f;

#pragma unroll
    for (int ks = 0; ks < 16; ks++) {
        uint32_t af[4];
        {
            float4 v = *reinterpret_cast<const float4*>(
                &As[((wm * 16 + ks) << 7) + (lane << 2)]);
            af[0] = __float_as_uint(v.x); af[1] = __float_as_uint(v.y);
            af[2] = __float_as_uint(v.z); af[3] = __float_as_uint(v.w);
        }
        uint32_t bf[4][2];
#pragma unroll
        for (int ni = 0; ni < 4; ni++) {
            float2 v = *reinterpret_cast<const float2*>(
                &Bs[(((wn * 4 + ni) * 16 + ks) << 6) + (lane << 1)]);
            bf[ni][0] = __float_as_uint(v.x); bf[ni][1] = __float_as_uint(v.y);
        }
#pragma unroll
        for (int ni = 0; ni < 4; ni++)
            mma_tf32(acc[ni][0], acc[ni][1], acc[ni][2], acc[ni][3],
                     af[0], af[1], af[2], af[3], bf[ni][0], bf[ni][1]);
    }

    int grp = lane >> 2, qd = lane & 3;
    float asr[2][2], adr[2][2];   // [rowhalf][headpair]
    if (MODE == 0) {
#pragma unroll
        for (int rh = 0; rh < 2; rh++)
#pragma unroll
            for (int hp = 0; hp < 2; hp++) { asr[rh][hp] = 0.f; adr[rh][hp] = 0.f; }
    }

#pragma unroll
    for (int ni = 0; ni < 4; ni++) {
        int cb = colbase + wn * 32 + ni * 8 + (qd << 1);
        int r = row0 + wm * 16 + grp;
        float v0 = acc[ni][0], v1 = acc[ni][1];
        float v2 = acc[ni][2], v3 = acc[ni][3];
        if (MODE == 1) {
            float b0 = aux0[cb], b1 = aux0[cb + 1];
            v0 = fmaxf(v0 + b0, 0.f); v1 = fmaxf(v1 + b1, 0.f);
            v2 = fmaxf(v2 + b0, 0.f); v3 = fmaxf(v3 + b1, 0.f);
        }
        if (MODE == 0) {
            int hp = ni >> 1;
            float a0 = aux0[cb], a1 = aux0[cb + 1];
            float d0 = aux1[cb], d1 = aux1[cb + 1];
            asr[0][hp] += v0 * a0 + v1 * a1;
            asr[1][hp] += v2 * a0 + v3 * a1;
            adr[0][hp] += v0 * d0 + v1 * d1;
            adr[1][hp] += v2 * d0 + v3 * d1;
        }
        if (r < nrows)
            *reinterpret_cast<float2*>(&C[(size_t)r * ncols + cb]) = make_float2(v0, v1);
        if (r + 8 < nrows)
            *reinterpret_cast<float2*>(&C[(size_t)(r + 8) * ncols + cb]) = make_float2(v2, v3);
    }

    if (MODE == 0) {
        // reduce over the 4 quad lanes (same grp)
#pragma unroll
        for (int rh = 0; rh < 2; rh++)
#pragma unroll
            for (int hp = 0; hp < 2; hp++) {
                float a = asr[rh][hp], d = adr[rh][hp];
                a += __shfl_xor_sync(0xffffffffu, a, 1);
                a += __shfl_xor_sync(0xffffffffu, a, 2);
                d += __shfl_xor_sync(0xffffffffu, d, 1);
                d += __shfl_xor_sync(0xffffffffu, d, 2);
                asr[rh][hp] = a; adr[rh][hp] = d;
            }
        if (qd == 0) {
            int h0 = (colbase + wn * 32) >> 4;
#pragma unroll
            for (int rh = 0; rh < 2; rh++) {
                int r = row0 + wm * 16 + grp + rh * 8;
                if (r < nrows) {
#pragma unroll
                    for (int hp = 0; hp < 2; hp++) {
                        g_as[r * 8 + h0 + hp] = asr[rh][hp];
                        g_ad[r * 8 + h0 + hp] = adr[rh][hp];
                    }
                }
            }
        }
    }
}

// ---------------- input projection: h = x @ W_in + b_in --------------------
__global__ void input_proj(const float* __restrict__ x,
                           const float* __restrict__ W_in,
                           const float* __restrict__ b_in) {
    int idx = blockIdx.x * blockDim.x + threadIdx.x;
    if (idx >= NN * HH) return;
    int n = idx >> 7, j = idx & 127;
    g_h[idx] = x[n * 2] * W_in[j] + x[n * 2 + 1] * W_in[128 + j] + b_in[j];
}

// ---------------- CSR build (R4-proven 3-phase scan) ------------------------
__global__ void count_kernel(const int* __restrict__ dst) {
    int e = blockIdx.x * blockDim.x + threadIdx.x;
    if (e < EE) atomicAdd(&g_cnt[dst[e]], 1);
}
__global__ void scan1() {
    __shared__ int sm[512];
    int i = blockIdx.x * 512 + threadIdx.x;
    int v = (i < NN) ? g_cnt[i] : 0;
    sm[threadIdx.x] = v;
    __syncthreads();
    for (int off = 1; off < 512; off <<= 1) {
        int t = (threadIdx.x >= off) ? sm[threadIdx.x - off] : 0;
        __syncthreads();
        sm[threadIdx.x] += t;
        __syncthreads();
    }
    if (i < NN) g_incl[i] = sm[threadIdx.x];
    if (threadIdx.x == 511) g_bsum[blockIdx.x] = sm[511];
}
__global__ void scan2(int nch) {
    __shared__ int sm[128];
    int v = (threadIdx.x < nch) ? g_bsum[threadIdx.x] : 0;
    sm[threadIdx.x] = v;
    __syncthreads();
    for (int off = 1; off < 128; off <<= 1) {
        int t = (threadIdx.x >= off) ? sm[threadIdx.x - off] : 0;
        __syncthreads();
        sm[threadIdx.x] += t;
        __syncthreads();
    }
    if (threadIdx.x < nch) g_bofs[threadIdx.x] = sm[threadIdx.x] - v;
}
__global__ void scan3() {
    int i = blockIdx.x * blockDim.x + threadIdx.x;
    if (i < NN) {
        int off = g_incl[i] - g_cnt[i] + g_bofs[i >> 9];
        g_rowoff[i] = off;
        g_cursor[i] = off;
    }
    if (i == 0) g_rowoff[NN] = EE;
}
__global__ void scatter(const int* __restrict__ src, const int* __restrict__ dst) {
    int e = blockIdx.x * blockDim.x + threadIdx.x;
    if (e < EE) {
        int d = dst[e];
        int pos = atomicAdd(&g_cursor[d], 1);
        g_csr[pos] = src[e];
    }
}

__device__ __forceinline__ float lrelu(float t) { return t > 0.f ? t : 0.2f * t; }

// ---------------- warp-per-node softmax aggregate (R4-proven two-pass) ------
__global__ void __launch_bounds__(256) aggregate_kernel(
    const float* __restrict__ gb, const float* __restrict__ lng,
    const float* __restrict__ lnb) {
    int n = (blockIdx.x * blockDim.x + threadIdx.x) >> 5;
    if (n >= NN) return;
    int lane = threadIdx.x & 31;
    int beg = g_rowoff[n], end = g_rowoff[n + 1];

    float adl = (lane < 8) ? g_ad[n * 8 + lane] : 0.f;
    float asl = (lane < 8) ? g_as[n * 8 + lane] : 0.f;
    float adv[8], selfl[8];
#pragma unroll
    for (int hh = 0; hh < 8; hh++) {
        adv[hh] = __shfl_sync(0xffffffffu, adl, hh);
        float s = __shfl_sync(0xffffffffu, asl, hh);
        selfl[hh] = lrelu(s + adv[hh]);
    }
    // pass 1: denominator (self loop included on lane 0)
    float dsum[8];
#pragma unroll
    for (int hh = 0; hh < 8; hh++)
        dsum[hh] = (lane == 0) ? __expf(selfl[hh]) : 0.f;
    for (int i = beg + lane; i < end; i += 32) {
        int s = g_csr[i];
#pragma unroll
        for (int hh = 0; hh < 8; hh++)
            dsum[hh] += __expf(lrelu(g_as[s * 8 + hh] + adv[hh]));
    }
#pragma unroll
    for (int hh = 0; hh < 8; hh++)
#pragma unroll
        for (int off = 16; off; off >>= 1)
            dsum[hh] += __shfl_xor_sync(0xffffffffu, dsum[hh], off);
    float invd[8];
#pragma unroll
    for (int hh = 0; hh < 8; hh++) invd[hh] = 1.0f / dsum[hh];

    // pass 2: weighted aggregation; lane owns dims [4*lane,4*lane+4)
    int c0 = lane * 4;
    int mh = lane >> 2;
    float iv = 0.f, sl = 0.f;
#pragma unroll
    for (int hh = 0; hh < 8; hh++)
        if (mh == hh) { iv = invd[hh]; sl = selfl[hh]; }
    float admh = __shfl_sync(0xffffffffu, adl, mh);

    float a0, a1, a2, a3;
    {
        float wgt = __expf(sl) * iv;  // self loop
        float4 v = *reinterpret_cast<const float4*>(&g_hw[(size_t)n * 128 + c0]);
        a0 = v.x * wgt; a1 = v.y * wgt; a2 = v.z * wgt; a3 = v.w * wgt;
    }
    for (int i = beg; i < end; i++) {
        int s = g_csr[i];
        float t = lrelu(g_as[s * 8 + mh] + admh);
        float wgt = __expf(t) * iv;
        float4 v = *reinterpret_cast<const float4*>(&g_hw[(size_t)s * 128 + c0]);
        a0 = fmaf(v.x, wgt, a0);
        a1 = fmaf(v.y, wgt, a1);
        a2 = fmaf(v.z, wgt, a2);
        a3 = fmaf(v.w, wgt, a3);
    }
    // epilogue: + gat bias, relu, + residual, LayerNorm
    float4 b4 = *reinterpret_cast<const float4*>(&gb[c0]);
    float v0 = fmaxf(a0 + b4.x, 0.f), v1 = fmaxf(a1 + b4.y, 0.f);
    float v2 = fmaxf(a2 + b4.z, 0.f), v3 = fmaxf(a3 + b4.w, 0.f);
    float4 r4 = *reinterpret_cast<const float4*>(&g_h[(size_t)n * 128 + c0]);
    v0 += r4.x; v1 += r4.y; v2 += r4.z; v3 += r4.w;
    float s1 = v0 + v1 + v2 + v3;
    float s2 = v0 * v0 + v1 * v1 + v2 * v2 + v3 * v3;
#pragma unroll
    for (int off = 16; off; off >>= 1) {
        s1 += __shfl_xor_sync(0xffffffffu, s1, off);
        s2 += __shfl_xor_sync(0xffffffffu, s2, off);
    }
    float mu = s1 * (1.f / 128.f);
    float var = s2 * (1.f / 128.f) - mu * mu;
    float rstd = rsqrtf(fmaxf(var, 0.f) + 1e-5f);
    float4 g4 = *reinterpret_cast<const float4*>(&lng[c0]);
    float4 bb4 = *reinterpret_cast<const float4*>(&lnb[c0]);
    float4 o;
    o.x = (v0 - mu) * rstd * g4.x + bb4.x;
    o.y = (v1 - mu) * rstd * g4.y + bb4.y;
    o.z = (v2 - mu) * rstd * g4.z + bb4.z;
    o.w = (v3 - mu) * rstd * g4.w + bb4.w;
    *reinterpret_cast<float4*>(&g_h[(size_t)n * 128 + c0]) = o;
}

// ---------------- MLP head final: out = t2 @ W3 + b3 ------------------------
__global__ void head_kernel(const float* __restrict__ W3,
                            const float* __restrict__ b3,
                            float* __restrict__ out) {
    int w = (blockIdx.x * blockDim.x + threadIdx.x) >> 5;
    int lane = threadIdx.x & 31;
    if (w >= NN) return;
    float2 a = *reinterpret_cast<const float2*>(&g_h[(size_t)w * 64 + lane * 2]);
    float2 wv = *reinterpret_cast<const float2*>(&W3[lane * 2]);
    float s = a.x * wv.x + a.y * wv.y;
#pragma unroll
    for (int off = 16; off; off >>= 1) s += __shfl_xor_sync(0xffffffffu, s, off);
    if (lane == 0) out[w] = s + b3[0];
}

// ---------------- launch ----------------------------------------------------
extern "C" void kernel_launch(void* const* d_in, const int* in_sizes, int n_in,
                              void* d_out, int out_size) {
    const float* x = (const float*)d_in[0];
    const int* ei = (const int*)d_in[1];
    const int* src = ei;
    const int* dst = ei + EE;
    const float* W_in = (const float*)d_in[3];
    const float* b_in = (const float*)d_in[4];
    float* out = (float*)d_out;

    float *p_h = nullptr, *p_hw = nullptr;
    int* p_cnt = nullptr;
    cudaGetSymbolAddress((void**)&p_h, g_h);
    cudaGetSymbolAddress((void**)&p_hw, g_hw);
    cudaGetSymbolAddress((void**)&p_cnt, g_cnt);

    const int SMEM_GEMM = (16384 + 8192) * 4;  // 96 KB
    cudaFuncSetAttribute(mma_gemm<0>, cudaFuncAttributeMaxDynamicSharedMemorySize, SMEM_GEMM);
    cudaFuncSetAttribute(mma_gemm<1>, cudaFuncAttributeMaxDynamicSharedMemorySize, SMEM_GEMM);
    const int NCTA = (NN + 127) / 128;  // 391

    input_proj<<<(NN * HH + 255) / 256, 256>>>(x, W_in, b_in);

    cudaMemsetAsync(p_cnt, 0, NN * sizeof(int));
    count_kernel<<<(EE + 255) / 256, 256>>>(dst);
    scan1<<<(NN + 511) / 512, 512>>>();
    scan2<<<1, 128>>>((NN + 511) / 512);
    scan3<<<(NN + 255) / 256, 256>>>();
    scatter<<<(EE + 255) / 256, 256>>>(src, dst);

    for (int l = 0; l < 3; l++) {
        const float* W  = (const float*)d_in[5 + 6 * l];
        const float* as = (const float*)d_in[6 + 6 * l];
        const float* ad = (const float*)d_in[7 + 6 * l];
        const float* gb = (const float*)d_in[8 + 6 * l];
        const float* lg = (const float*)d_in[9 + 6 * l];
        const float* lb = (const float*)d_in[10 + 6 * l];
        mma_gemm<0><<<dim3(NCTA, 2), 512, SMEM_GEMM>>>(p_h, W, 128, as, ad, p_hw, NN);
        aggregate_kernel<<<(NN + 7) / 8, 256>>>(gb, lg, lb);
    }
    // MLP head
    mma_gemm<1><<<dim3(NCTA, 2), 512, SMEM_GEMM>>>(p_h, (const float*)d_in[23], 128,
                                                   (const float*)d_in[24], nullptr, p_hw, NN);
    mma_gemm<1><<<dim3(NCTA, 1), 512, SMEM_GEMM>>>(p_hw, (const float*)d_in[25], 64,
                                                   (const float*)d_in[26], nullptr, p_h, NN);
    head_kernel<<<(NN * 32 + 255) / 256, 256>>>((const float*)d_in[27],
                                                (const float*)d_in[28], out);
}

// round 8
// speedup vs baseline: 2.0766x; 1.1671x over previous
#include <cuda_runtime.h>
#include <math.h>
#include <stdint.h>

#define NN 50000
#define EE 600000
#define HH 128

// ---------------- static device scratch (no allocs allowed) ----------------
__device__ float g_h[NN * HH];      // current node features
__device__ float g_hw[NN * HH];     // h @ W
__device__ float g_as[NN * 8];      // alpha_src per node/head
__device__ float g_ad[NN * 8];      // alpha_dst per node/head
__device__ int   g_cnt[NN];
__device__ int   g_incl[NN];
__device__ int   g_rowoff[NN + 1];
__device__ int   g_cursor[NN];
__device__ int   g_bsum[128];
__device__ int   g_bofs[128];
__device__ int   g_csr[EE];

// ---------------- tf32 helpers ----------------------------------------------
__device__ __forceinline__ uint32_t f2tf32(float v) {
    uint32_t t;
    asm("cvt.rna.tf32.f32 %0, %1;" : "=r"(t) : "f"(v));
    return t;
}
__device__ __forceinline__ void mma_tf32(float& c0, float& c1, float& c2, float& c3,
                                         uint32_t a0, uint32_t a1, uint32_t a2, uint32_t a3,
                                         uint32_t b0, uint32_t b1) {
    asm volatile(
        "mma.sync.aligned.m16n8k8.row.col.f32.tf32.tf32.f32 "
        "{%0,%1,%2,%3}, {%4,%5,%6,%7}, {%8,%9}, {%0,%1,%2,%3};"
        : "+f"(c0), "+f"(c1), "+f"(c2), "+f"(c3)
        : "r"(a0), "r"(a1), "r"(a2), "r"(a3), "r"(b0), "r"(b1));
}

// A fragment-layout index for element (r, c) within the 128x128 tile
__device__ __forceinline__ int a_idx(int r, int c) {
    int mt = r >> 4, rr = r & 15, ks = c >> 3;
    int ln = ((rr & 7) << 2) | (c & 3);
    int rg = (rr >> 3) | (((c >> 2) & 1) << 1);
    return ((mt * 16 + ks) << 7) + (ln << 2) + rg;
}

// ---------------- HMMA tf32 GEMM: C[rows, ncols] = A[rows,128] @ W[128,ncols]
// CTA tile: 128 rows x 64 cols (col tile = blockIdx.y), 256 threads (R4 shape).
// Pipelined: stage B + A-ksteps[0..7]; prefetch A-ksteps[8..15] into regs;
// compute first half while loads are in flight; STS; compute second half.
// MODE 0: store C + fused per-head attention dots (aux0=a_src, aux1=a_dst)
// MODE 1: bias (aux0) + relu
template <int MODE>
__global__ void __launch_bounds__(256, 2) mma_gemm(
    const float* __restrict__ A, const float* __restrict__ W, int ncols,
    const float* __restrict__ aux0, const float* __restrict__ aux1,
    float* __restrict__ C, int nrows) {
    extern __shared__ float sm[];
    float* As = sm;              // [8 mtile][16 kstep][128] = 16384 floats
    float* Bs = sm + 16384;      // [8 ntile][16 kstep][64]  = 8192 floats
    int tid = threadIdx.x;
    int row0 = blockIdx.x * 128;
    int colbase = blockIdx.y * 64;

    // stage W cols [colbase,colbase+64) -> fragment-major, float4 global loads
    for (int i = tid * 4; i < 128 * 64; i += 256 * 4) {
        int k = i >> 6, n = i & 63;
        float4 wv = *reinterpret_cast<const float4*>(&W[(size_t)k * ncols + colbase + n]);
#pragma unroll
        for (int e = 0; e < 4; e++) {
            int nn0 = n + e;
            int nt = nn0 >> 3, nnn = nn0 & 7, ks = k >> 3;
            int ln = (nnn << 2) | (k & 3);
            int rg = (k >> 2) & 1;
            Bs[((nt * 16 + ks) << 6) + (ln << 1) + rg] = __uint_as_float(f2tf32((&wv.x)[e]));
        }
    }
    // stage A ksteps 0..7 (cols 0..63): 2048 float4 groups
    for (int g = tid; g < 2048; g += 256) {
        int r = g >> 4, c = (g & 15) * 4;
        int gr = row0 + r; if (gr >= nrows) gr = nrows - 1;
        float4 v = *reinterpret_cast<const float4*>(&A[(size_t)gr * 128 + c]);
#pragma unroll
        for (int e = 0; e < 4; e++)
            As[a_idx(r, c + e)] = __uint_as_float(f2tf32((&v.x)[e]));
    }
    // prefetch A ksteps 8..15 (cols 64..127) into registers
    float4 pf[8];
#pragma unroll
    for (int j = 0; j < 8; j++) {
        int g = j * 256 + tid;
        int r = g >> 4, c = 64 + (g & 15) * 4;
        int gr = row0 + r; if (gr >= nrows) gr = nrows - 1;
        pf[j] = *reinterpret_cast<const float4*>(&A[(size_t)gr * 128 + c]);
    }
    __syncthreads();

    int w = tid >> 5, lane = tid & 31;
    int wm = w >> 1, wn = w & 1;
    float acc[2][4][4];
#pragma unroll
    for (int mi = 0; mi < 2; mi++)
#pragma unroll
        for (int ni = 0; ni < 4; ni++)
#pragma unroll
            for (int j = 0; j < 4; j++) acc[mi][ni][j] = 0.f;

    // ---- compute ksteps 0..7 (prefetched loads still in flight) ----
#pragma unroll
    for (int ks = 0; ks < 8; ks++) {
        uint32_t af[2][4];
#pragma unroll
        for (int mi = 0; mi < 2; mi++) {
            float4 v = *reinterpret_cast<const float4*>(
                &As[(((wm * 2 + mi) * 16 + ks) << 7) + (lane << 2)]);
            af[mi][0] = __float_as_uint(v.x); af[mi][1] = __float_as_uint(v.y);
            af[mi][2] = __float_as_uint(v.z); af[mi][3] = __float_as_uint(v.w);
        }
        uint32_t bf[4][2];
#pragma unroll
        for (int ni = 0; ni < 4; ni++) {
            float2 v = *reinterpret_cast<const float2*>(
                &Bs[(((wn * 4 + ni) * 16 + ks) << 6) + (lane << 1)]);
            bf[ni][0] = __float_as_uint(v.x); bf[ni][1] = __float_as_uint(v.y);
        }
#pragma unroll
        for (int mi = 0; mi < 2; mi++)
#pragma unroll
            for (int ni = 0; ni < 4; ni++)
                mma_tf32(acc[mi][ni][0], acc[mi][ni][1], acc[mi][ni][2], acc[mi][ni][3],
                         af[mi][0], af[mi][1], af[mi][2], af[mi][3],
                         bf[ni][0], bf[ni][1]);
    }
    __syncthreads();
    // ---- store prefetched A half ----
#pragma unroll
    for (int j = 0; j < 8; j++) {
        int g = j * 256 + tid;
        int r = g >> 4, c = 64 + (g & 15) * 4;
#pragma unroll
        for (int e = 0; e < 4; e++)
            As[a_idx(r, c + e)] = __uint_as_float(f2tf32((&pf[j].x)[e]));
    }
    __syncthreads();
    // ---- compute ksteps 8..15 ----
#pragma unroll
    for (int ks = 8; ks < 16; ks++) {
        uint32_t af[2][4];
#pragma unroll
        for (int mi = 0; mi < 2; mi++) {
            float4 v = *reinterpret_cast<const float4*>(
                &As[(((wm * 2 + mi) * 16 + ks) << 7) + (lane << 2)]);
            af[mi][0] = __float_as_uint(v.x); af[mi][1] = __float_as_uint(v.y);
            af[mi][2] = __float_as_uint(v.z); af[mi][3] = __float_as_uint(v.w);
        }
        uint32_t bf[4][2];
#pragma unroll
        for (int ni = 0; ni < 4; ni++) {
            float2 v = *reinterpret_cast<const float2*>(
                &Bs[(((wn * 4 + ni) * 16 + ks) << 6) + (lane << 1)]);
            bf[ni][0] = __float_as_uint(v.x); bf[ni][1] = __float_as_uint(v.y);
        }
#pragma unroll
        for (int mi = 0; mi < 2; mi++)
#pragma unroll
            for (int ni = 0; ni < 4; ni++)
                mma_tf32(acc[mi][ni][0], acc[mi][ni][1], acc[mi][ni][2], acc[mi][ni][3],
                         af[mi][0], af[mi][1], af[mi][2], af[mi][3],
                         bf[ni][0], bf[ni][1]);
    }

    int grp = lane >> 2, qd = lane & 3;
    float asr[2][2][2], adr[2][2][2];
    if (MODE == 0) {
#pragma unroll
        for (int mi = 0; mi < 2; mi++)
#pragma unroll
            for (int rh = 0; rh < 2; rh++)
#pragma unroll
                for (int hp = 0; hp < 2; hp++) { asr[mi][rh][hp] = 0.f; adr[mi][rh][hp] = 0.f; }
    }

#pragma unroll
    for (int mi = 0; mi < 2; mi++) {
#pragma unroll
        for (int ni = 0; ni < 4; ni++) {
            int cb = colbase + wn * 32 + ni * 8 + (qd << 1);
            int r = row0 + wm * 32 + mi * 16 + grp;
            float v0 = acc[mi][ni][0], v1 = acc[mi][ni][1];
            float v2 = acc[mi][ni][2], v3 = acc[mi][ni][3];
            if (MODE == 1) {
                float b0 = aux0[cb], b1 = aux0[cb + 1];
                v0 = fmaxf(v0 + b0, 0.f); v1 = fmaxf(v1 + b1, 0.f);
                v2 = fmaxf(v2 + b0, 0.f); v3 = fmaxf(v3 + b1, 0.f);
            }
            if (MODE == 0) {
                int hp = ni >> 1;
                float a0 = aux0[cb], a1 = aux0[cb + 1];
                float d0 = aux1[cb], d1 = aux1[cb + 1];
                asr[mi][0][hp] += v0 * a0 + v1 * a1;
                asr[mi][1][hp] += v2 * a0 + v3 * a1;
                adr[mi][0][hp] += v0 * d0 + v1 * d1;
                adr[mi][1][hp] += v2 * d0 + v3 * d1;
            }
            if (r < nrows)
                *reinterpret_cast<float2*>(&C[(size_t)r * ncols + cb]) = make_float2(v0, v1);
            if (r + 8 < nrows)
                *reinterpret_cast<float2*>(&C[(size_t)(r + 8) * ncols + cb]) = make_float2(v2, v3);
        }
    }

    if (MODE == 0) {
#pragma unroll
        for (int mi = 0; mi < 2; mi++)
#pragma unroll
            for (int rh = 0; rh < 2; rh++)
#pragma unroll
                for (int hp = 0; hp < 2; hp++) {
                    float a = asr[mi][rh][hp], d = adr[mi][rh][hp];
                    a += __shfl_xor_sync(0xffffffffu, a, 1);
                    a += __shfl_xor_sync(0xffffffffu, a, 2);
                    d += __shfl_xor_sync(0xffffffffu, d, 1);
                    d += __shfl_xor_sync(0xffffffffu, d, 2);
                    asr[mi][rh][hp] = a; adr[mi][rh][hp] = d;
                }
        if (qd == 0) {
            int h0 = (colbase + wn * 32) >> 4;
#pragma unroll
            for (int mi = 0; mi < 2; mi++)
#pragma unroll
                for (int rh = 0; rh < 2; rh++) {
                    int r = row0 + wm * 32 + mi * 16 + grp + rh * 8;
                    if (r < nrows) {
#pragma unroll
                        for (int hp = 0; hp < 2; hp++) {
                            g_as[r * 8 + h0 + hp] = asr[mi][rh][hp];
                            g_ad[r * 8 + h0 + hp] = adr[mi][rh][hp];
                        }
                    }
                }
        }
    }
}

// ---------------- input projection: h = x @ W_in + b_in --------------------
__global__ void input_proj(const float* __restrict__ x,
                           const float* __restrict__ W_in,
                           const float* __restrict__ b_in) {
    int idx = blockIdx.x * blockDim.x + threadIdx.x;
    if (idx >= NN * HH) return;
    int n = idx >> 7, j = idx & 127;
    g_h[idx] = x[n * 2] * W_in[j] + x[n * 2 + 1] * W_in[128 + j] + b_in[j];
}

// ---------------- CSR build (R4-proven 3-phase scan) ------------------------
__global__ void count_kernel(const int* __restrict__ dst) {
    int e = blockIdx.x * blockDim.x + threadIdx.x;
    if (e < EE) atomicAdd(&g_cnt[dst[e]], 1);
}
__global__ void scan1() {
    __shared__ int sm[512];
    int i = blockIdx.x * 512 + threadIdx.x;
    int v = (i < NN) ? g_cnt[i] : 0;
    sm[threadIdx.x] = v;
    __syncthreads();
    for (int off = 1; off < 512; off <<= 1) {
        int t = (threadIdx.x >= off) ? sm[threadIdx.x - off] : 0;
        __syncthreads();
        sm[threadIdx.x] += t;
        __syncthreads();
    }
    if (i < NN) g_incl[i] = sm[threadIdx.x];
    if (threadIdx.x == 511) g_bsum[blockIdx.x] = sm[511];
}
__global__ void scan2(int nch) {
    __shared__ int sm[128];
    int v = (threadIdx.x < nch) ? g_bsum[threadIdx.x] : 0;
    sm[threadIdx.x] = v;
    __syncthreads();
    for (int off = 1; off < 128; off <<= 1) {
        int t = (threadIdx.x >= off) ? sm[threadIdx.x - off] : 0;
        __syncthreads();
        sm[threadIdx.x] += t;
        __syncthreads();
    }
    if (threadIdx.x < nch) g_bofs[threadIdx.x] = sm[threadIdx.x] - v;
}
__global__ void scan3() {
    int i = blockIdx.x * blockDim.x + threadIdx.x;
    if (i < NN) {
        int off = g_incl[i] - g_cnt[i] + g_bofs[i >> 9];
        g_rowoff[i] = off;
        g_cursor[i] = off;
    }
    if (i == 0) g_rowoff[NN] = EE;
}
__global__ void scatter(const int* __restrict__ src, const int* __restrict__ dst) {
    int e = blockIdx.x * blockDim.x + threadIdx.x;
    if (e < EE) {
        int d = dst[e];
        int pos = atomicAdd(&g_cursor[d], 1);
        g_csr[pos] = src[e];
    }
}

__device__ __forceinline__ float lrelu(float t) { return t > 0.f ? t : 0.2f * t; }

// ---------------- ONE-sweep softmax aggregate + bias+relu+res+LN ------------
// warp per node; lane owns dims [4*lane, 4*lane+4), head mh = lane>>2.
// Denominator accumulates in the same loop as the numerator (no-max softmax);
// final scale by 1/den. 2-way edge unroll for ILP.
__global__ void __launch_bounds__(256) aggregate_kernel(
    const float* __restrict__ gb, const float* __restrict__ lng,
    const float* __restrict__ lnb) {
    int n = (blockIdx.x * blockDim.x + threadIdx.x) >> 5;
    if (n >= NN) return;
    int lane = threadIdx.x & 31;
    int beg = g_rowoff[n], end = g_rowoff[n + 1];
    int mh = lane >> 2;
    int c0 = lane * 4;

    float admh = g_ad[n * 8 + mh];   // quad-uniform (broadcast)
    float asmh = g_as[n * 8 + mh];
    float wself = __expf(lrelu(asmh + admh));
    float den = wself;
    float a0, a1, a2, a3;
    {
        float4 v = *reinterpret_cast<const float4*>(&g_hw[(size_t)n * 128 + c0]);
        a0 = v.x * wself; a1 = v.y * wself; a2 = v.z * wself; a3 = v.w * wself;
    }
    int i = beg;
    for (; i + 2 <= end; i += 2) {
        int s0 = g_csr[i], s1 = g_csr[i + 1];
        float w0 = __expf(lrelu(g_as[s0 * 8 + mh] + admh));
        float w1 = __expf(lrelu(g_as[s1 * 8 + mh] + admh));
        float4 v0 = *reinterpret_cast<const float4*>(&g_hw[(size_t)s0 * 128 + c0]);
        float4 v1 = *reinterpret_cast<const float4*>(&g_hw[(size_t)s1 * 128 + c0]);
        den += w0 + w1;
        a0 = fmaf(v0.x, w0, fmaf(v1.x, w1, a0));
        a1 = fmaf(v0.y, w0, fmaf(v1.y, w1, a1));
        a2 = fmaf(v0.z, w0, fmaf(v1.z, w1, a2));
        a3 = fmaf(v0.w, w0, fmaf(v1.w, w1, a3));
    }
    if (i < end) {
        int s = g_csr[i];
        float wgt = __expf(lrelu(g_as[s * 8 + mh] + admh));
        float4 v = *reinterpret_cast<const float4*>(&g_hw[(size_t)s * 128 + c0]);
        den += wgt;
        a0 = fmaf(v.x, wgt, a0);
        a1 = fmaf(v.y, wgt, a1);
        a2 = fmaf(v.z, wgt, a2);
        a3 = fmaf(v.w, wgt, a3);
    }
    float iv = 1.0f / den;
    // epilogue: + gat bias, relu, + residual, LayerNorm
    float4 b4 = *reinterpret_cast<const float4*>(&gb[c0]);
    float v0 = fmaxf(fmaf(a0, iv, b4.x), 0.f), v1 = fmaxf(fmaf(a1, iv, b4.y), 0.f);
    float v2 = fmaxf(fmaf(a2, iv, b4.z), 0.f), v3 = fmaxf(fmaf(a3, iv, b4.w), 0.f);
    float4 r4 = *reinterpret_cast<const float4*>(&g_h[(size_t)n * 128 + c0]);
    v0 += r4.x; v1 += r4.y; v2 += r4.z; v3 += r4.w;
    float s1 = v0 + v1 + v2 + v3;
    float s2 = v0 * v0 + v1 * v1 + v2 * v2 + v3 * v3;
#pragma unroll
    for (int off = 16; off; off >>= 1) {
        s1 += __shfl_xor_sync(0xffffffffu, s1, off);
        s2 += __shfl_xor_sync(0xffffffffu, s2, off);
    }
    float mu = s1 * (1.f / 128.f);
    float var = s2 * (1.f / 128.f) - mu * mu;
    float rstd = rsqrtf(fmaxf(var, 0.f) + 1e-5f);
    float4 g4 = *reinterpret_cast<const float4*>(&lng[c0]);
    float4 bb4 = *reinterpret_cast<const float4*>(&lnb[c0]);
    float4 o;
    o.x = (v0 - mu) * rstd * g4.x + bb4.x;
    o.y = (v1 - mu) * rstd * g4.y + bb4.y;
    o.z = (v2 - mu) * rstd * g4.z + bb4.z;
    o.w = (v3 - mu) * rstd * g4.w + bb4.w;
    *reinterpret_cast<float4*>(&g_h[(size_t)n * 128 + c0]) = o;
}

// ---------------- MLP head final: out = t2 @ W3 + b3 ------------------------
__global__ void head_kernel(const float* __restrict__ W3,
                            const float* __restrict__ b3,
                            float* __restrict__ out) {
    int w = (blockIdx.x * blockDim.x + threadIdx.x) >> 5;
    int lane = threadIdx.x & 31;
    if (w >= NN) return;
    float2 a = *reinterpret_cast<const float2*>(&g_h[(size_t)w * 64 + lane * 2]);
    float2 wv = *reinterpret_cast<const float2*>(&W3[lane * 2]);
    float s = a.x * wv.x + a.y * wv.y;
#pragma unroll
    for (int off = 16; off; off >>= 1) s += __shfl_xor_sync(0xffffffffu, s, off);
    if (lane == 0) out[w] = s + b3[0];
}

// ---------------- launch ----------------------------------------------------
extern "C" void kernel_launch(void* const* d_in, const int* in_sizes, int n_in,
                              void* d_out, int out_size) {
    const float* x = (const float*)d_in[0];
    const int* ei = (const int*)d_in[1];
    const int* src = ei;
    const int* dst = ei + EE;
    const float* W_in = (const float*)d_in[3];
    const float* b_in = (const float*)d_in[4];
    float* out = (float*)d_out;

    float *p_h = nullptr, *p_hw = nullptr;
    int* p_cnt = nullptr;
    cudaGetSymbolAddress((void**)&p_h, g_h);
    cudaGetSymbolAddress((void**)&p_hw, g_hw);
    cudaGetSymbolAddress((void**)&p_cnt, g_cnt);

    const int SMEM_GEMM = (16384 + 8192) * 4;  // 96 KB
    cudaFuncSetAttribute(mma_gemm<0>, cudaFuncAttributeMaxDynamicSharedMemorySize, SMEM_GEMM);
    cudaFuncSetAttribute(mma_gemm<1>, cudaFuncAttributeMaxDynamicSharedMemorySize, SMEM_GEMM);
    const int NCTA = (NN + 127) / 128;  // 391

    input_proj<<<(NN * HH + 255) / 256, 256>>>(x, W_in, b_in);

    cudaMemsetAsync(p_cnt, 0, NN * sizeof(int));
    count_kernel<<<(EE + 255) / 256, 256>>>(dst);
    scan1<<<(NN + 511) / 512, 512>>>();
    scan2<<<1, 128>>>((NN + 511) / 512);
    scan3<<<(NN + 255) / 256, 256>>>();
    scatter<<<(EE + 255) / 256, 256>>>(src, dst);

    for (int l = 0; l < 3; l++) {
        const float* W  = (const float*)d_in[5 + 6 * l];
        const float* as = (const float*)d_in[6 + 6 * l];
        const float* ad = (const float*)d_in[7 + 6 * l];
        const float* gb = (const float*)d_in[8 + 6 * l];
        const float* lg = (const float*)d_in[9 + 6 * l];
        const float* lb = (const float*)d_in[10 + 6 * l];
        mma_gemm<0><<<dim3(NCTA, 2), 256, SMEM_GEMM>>>(p_h, W, 128, as, ad, p_hw, NN);
        aggregate_kernel<<<(NN + 7) / 8, 256>>>(gb, lg, lb);
    }
    // MLP head
    mma_gemm<1><<<dim3(NCTA, 2), 256, SMEM_GEMM>>>(p_h, (const float*)d_in[23], 128,
                                                   (const float*)d_in[24], nullptr, p_hw, NN);
    mma_gemm<1><<<dim3(NCTA, 1), 256, SMEM_GEMM>>>(p_hw, (const float*)d_in[25], 64,
                                                   (const float*)d_in[26], nullptr, p_h, NN);
    head_kernel<<<(NN * 32 + 255) / 256, 256>>>((const float*)d_in[27],
                                                (const float*)d_in[28], out);
}

// round 9
// speedup vs baseline: 2.2750x; 1.0955x over previous
#include <cuda_runtime.h>
#include <math.h>
#include <stdint.h>

#define NN 50000
#define EE 600000
#define HH 128

// ---------------- static device scratch (no allocs allowed) ----------------
__device__ float g_h[NN * HH];      // current node features
__device__ float g_hw[NN * HH];     // h @ W
__device__ float g_as[NN * 8];      // alpha_src per node/head
__device__ float g_ad[NN * 8];      // alpha_dst per node/head
__device__ int   g_cnt[NN];
__device__ int   g_incl[NN];
__device__ int   g_rowoff[NN + 1];
__device__ int   g_cursor[NN];
__device__ int   g_bsum[128];
__device__ int   g_bofs[128];
__device__ int   g_csr[EE];

// ---------------- tf32 helpers ----------------------------------------------
__device__ __forceinline__ uint32_t f2tf32(float v) {
    uint32_t t;
    asm("cvt.rna.tf32.f32 %0, %1;" : "=r"(t) : "f"(v));
    return t;
}
__device__ __forceinline__ void mma_tf32(float& c0, float& c1, float& c2, float& c3,
                                         uint32_t a0, uint32_t a1, uint32_t a2, uint32_t a3,
                                         uint32_t b0, uint32_t b1) {
    asm volatile(
        "mma.sync.aligned.m16n8k8.row.col.f32.tf32.tf32.f32 "
        "{%0,%1,%2,%3}, {%4,%5,%6,%7}, {%8,%9}, {%0,%1,%2,%3};"
        : "+f"(c0), "+f"(c1), "+f"(c2), "+f"(c3)
        : "r"(a0), "r"(a1), "r"(a2), "r"(a3), "r"(b0), "r"(b1));
}

// A fragment-layout index for element (r, c) within the 128x128 tile
__device__ __forceinline__ int a_idx(int r, int c) {
    int mt = r >> 4, rr = r & 15, ks = c >> 3;
    int ln = ((rr & 7) << 2) | (c & 3);
    int rg = (rr >> 3) | (((c >> 2) & 1) << 1);
    return ((mt * 16 + ks) << 7) + (ln << 2) + rg;
}
// B fragment-layout index for (col n, k) within a 64-col tile
__device__ __forceinline__ int b_idx(int n, int k) {
    int nt = n >> 3, nn = n & 7, ks = k >> 3;
    return ((nt * 16 + ks) << 6) + (((nn << 2) | (k & 3)) << 1) + ((k >> 2) & 1);
}

// ---------------- HMMA tf32 GEMM: C[rows, ncols] = A[rows,128] @ W[128,ncols]
// One CTA = 128 rows x ALL ncols (loops over 64-col tiles; A staged once).
// 8 warps: 4(m) x 2(n). Pipelined A halves; B(tile1) prefetched during
// tile-0 epilogue.
// MODE 0: store C + fused attention dots (aux0=a_src, aux1=a_dst)
// MODE 1: bias (aux0) + relu, store C
// MODE 2: bias (aux0) + relu + fused head dot with W3 (aux1), write out[row]
template <int MODE>
__global__ void __launch_bounds__(256, 2) mma_gemm(
    const float* __restrict__ A, const float* __restrict__ W, int ncols,
    const float* __restrict__ aux0, const float* __restrict__ aux1,
    float* __restrict__ C, int nrows,
    const float* __restrict__ b3, float* __restrict__ out) {
    extern __shared__ float sm[];
    float* As = sm;              // [8 mtile][16 kstep][128] = 16384 floats
    float* Bs = sm + 16384;      // [8 ntile][16 kstep][64]  = 8192 floats
    __shared__ float hsum[128];  // MODE 2 cross-warp head reduction
    int tid = threadIdx.x;
    int row0 = blockIdx.x * 128;
    int ntiles = ncols >> 6;

    int w = tid >> 5, lane = tid & 31;
    int wm = w >> 1, wn = w & 1;
    int grp = lane >> 2, qd = lane & 3;

    // ---- stage B tile 0 ----
#pragma unroll
    for (int j = 0; j < 8; j++) {
        int i = tid * 4 + j * 1024;
        int k = i >> 6, n = i & 63;
        float4 wv = *reinterpret_cast<const float4*>(&W[(size_t)k * ncols + n]);
#pragma unroll
        for (int e = 0; e < 4; e++)
            Bs[b_idx(n + e, k)] = __uint_as_float(f2tf32((&wv.x)[e]));
    }
    // ---- stage A ksteps 0..7 (cols 0..63) ----
    for (int g = tid; g < 2048; g += 256) {
        int r = g >> 4, c = (g & 15) * 4;
        int gr = row0 + r; if (gr >= nrows) gr = nrows - 1;
        float4 v = *reinterpret_cast<const float4*>(&A[(size_t)gr * 128 + c]);
#pragma unroll
        for (int e = 0; e < 4; e++)
            As[a_idx(r, c + e)] = __uint_as_float(f2tf32((&v.x)[e]));
    }
    // ---- prefetch A ksteps 8..15 into regs ----
    float4 pf[8];
#pragma unroll
    for (int j = 0; j < 8; j++) {
        int g = j * 256 + tid;
        int r = g >> 4, c = 64 + (g & 15) * 4;
        int gr = row0 + r; if (gr >= nrows) gr = nrows - 1;
        pf[j] = *reinterpret_cast<const float4*>(&A[(size_t)gr * 128 + c]);
    }
    __syncthreads();

    float acc[2][4][4];
    auto compute = [&](int ks0, int ks1) {
        for (int ks = ks0; ks < ks1; ks++) {
            uint32_t af[2][4];
#pragma unroll
            for (int mi = 0; mi < 2; mi++) {
                float4 v = *reinterpret_cast<const float4*>(
                    &As[(((wm * 2 + mi) * 16 + ks) << 7) + (lane << 2)]);
                af[mi][0] = __float_as_uint(v.x); af[mi][1] = __float_as_uint(v.y);
                af[mi][2] = __float_as_uint(v.z); af[mi][3] = __float_as_uint(v.w);
            }
            uint32_t bf[4][2];
#pragma unroll
            for (int ni = 0; ni < 4; ni++) {
                float2 v = *reinterpret_cast<const float2*>(
                    &Bs[(((wn * 4 + ni) * 16 + ks) << 6) + (lane << 1)]);
                bf[ni][0] = __float_as_uint(v.x); bf[ni][1] = __float_as_uint(v.y);
            }
#pragma unroll
            for (int mi = 0; mi < 2; mi++)
#pragma unroll
                for (int ni = 0; ni < 4; ni++)
                    mma_tf32(acc[mi][ni][0], acc[mi][ni][1], acc[mi][ni][2], acc[mi][ni][3],
                             af[mi][0], af[mi][1], af[mi][2], af[mi][3],
                             bf[ni][0], bf[ni][1]);
        }
    };

    auto epilogue = [&](int colbase) {
        float asr[2][2][2], adr[2][2][2];   // MODE 0
        float pr[2][2];                     // MODE 2 row partials
        if (MODE == 0) {
#pragma unroll
            for (int mi = 0; mi < 2; mi++)
#pragma unroll
                for (int rh = 0; rh < 2; rh++)
#pragma unroll
                    for (int hp = 0; hp < 2; hp++) { asr[mi][rh][hp] = 0.f; adr[mi][rh][hp] = 0.f; }
        }
        if (MODE == 2) { pr[0][0] = pr[0][1] = pr[1][0] = pr[1][1] = 0.f; }
#pragma unroll
        for (int mi = 0; mi < 2; mi++) {
#pragma unroll
            for (int ni = 0; ni < 4; ni++) {
                int cb = colbase + wn * 32 + ni * 8 + (qd << 1);
                int r = row0 + wm * 32 + mi * 16 + grp;
                float v0 = acc[mi][ni][0], v1 = acc[mi][ni][1];
                float v2 = acc[mi][ni][2], v3 = acc[mi][ni][3];
                if (MODE >= 1) {
                    float b0 = aux0[cb], b1 = aux0[cb + 1];
                    v0 = fmaxf(v0 + b0, 0.f); v1 = fmaxf(v1 + b1, 0.f);
                    v2 = fmaxf(v2 + b0, 0.f); v3 = fmaxf(v3 + b1, 0.f);
                }
                if (MODE == 0) {
                    int hp = ni >> 1;
                    float a0 = aux0[cb], a1 = aux0[cb + 1];
                    float d0 = aux1[cb], d1 = aux1[cb + 1];
                    asr[mi][0][hp] += v0 * a0 + v1 * a1;
                    asr[mi][1][hp] += v2 * a0 + v3 * a1;
                    adr[mi][0][hp] += v0 * d0 + v1 * d1;
                    adr[mi][1][hp] += v2 * d0 + v3 * d1;
                }
                if (MODE == 2) {
                    float w0 = aux1[cb], w1 = aux1[cb + 1];
                    pr[mi][0] += v0 * w0 + v1 * w1;
                    pr[mi][1] += v2 * w0 + v3 * w1;
                } else {
                    if (r < nrows)
                        *reinterpret_cast<float2*>(&C[(size_t)r * ncols + cb]) = make_float2(v0, v1);
                    if (r + 8 < nrows)
                        *reinterpret_cast<float2*>(&C[(size_t)(r + 8) * ncols + cb]) = make_float2(v2, v3);
                }
            }
        }
        if (MODE == 0) {
#pragma unroll
            for (int mi = 0; mi < 2; mi++)
#pragma unroll
                for (int rh = 0; rh < 2; rh++)
#pragma unroll
                    for (int hp = 0; hp < 2; hp++) {
                        float a = asr[mi][rh][hp], d = adr[mi][rh][hp];
                        a += __shfl_xor_sync(0xffffffffu, a, 1);
                        a += __shfl_xor_sync(0xffffffffu, a, 2);
                        d += __shfl_xor_sync(0xffffffffu, d, 1);
                        d += __shfl_xor_sync(0xffffffffu, d, 2);
                        asr[mi][rh][hp] = a; adr[mi][rh][hp] = d;
                    }
            if (qd == 0) {
                int h0 = (colbase + wn * 32) >> 4;
#pragma unroll
                for (int mi = 0; mi < 2; mi++)
#pragma unroll
                    for (int rh = 0; rh < 2; rh++) {
                        int r = row0 + wm * 32 + mi * 16 + grp + rh * 8;
                        if (r < nrows) {
#pragma unroll
                            for (int hp = 0; hp < 2; hp++) {
                                g_as[r * 8 + h0 + hp] = asr[mi][rh][hp];
                                g_ad[r * 8 + h0 + hp] = adr[mi][rh][hp];
                            }
                        }
                    }
            }
        }
        if (MODE == 2) {
            // reduce over quad lanes, then across the two n-warps via SMEM
#pragma unroll
            for (int mi = 0; mi < 2; mi++)
#pragma unroll
                for (int rh = 0; rh < 2; rh++) {
                    float p = pr[mi][rh];
                    p += __shfl_xor_sync(0xffffffffu, p, 1);
                    p += __shfl_xor_sync(0xffffffffu, p, 2);
                    pr[mi][rh] = p;
                }
            if (wn == 0 && qd == 0) {
#pragma unroll
                for (int mi = 0; mi < 2; mi++)
#pragma unroll
                    for (int rh = 0; rh < 2; rh++)
                        hsum[wm * 32 + mi * 16 + grp + rh * 8] = pr[mi][rh];
            }
            __syncthreads();
            if (wn == 1 && qd == 0) {
                float bb = b3[0];
#pragma unroll
                for (int mi = 0; mi < 2; mi++)
#pragma unroll
                    for (int rh = 0; rh < 2; rh++) {
                        int local = wm * 32 + mi * 16 + grp + rh * 8;
                        int r = row0 + local;
                        if (r < nrows) out[r] = hsum[local] + pr[mi][rh] + bb;
                    }
            }
        }
    };

    // ================= tile 0 =================
#pragma unroll
    for (int mi = 0; mi < 2; mi++)
#pragma unroll
        for (int ni = 0; ni < 4; ni++)
#pragma unroll
            for (int j = 0; j < 4; j++) acc[mi][ni][j] = 0.f;
    compute(0, 8);
    __syncthreads();
#pragma unroll
    for (int j = 0; j < 8; j++) {
        int g = j * 256 + tid;
        int r = g >> 4, c = 64 + (g & 15) * 4;
#pragma unroll
        for (int e = 0; e < 4; e++)
            As[a_idx(r, c + e)] = __uint_as_float(f2tf32((&pf[j].x)[e]));
    }
    __syncthreads();
    compute(8, 16);
    // prefetch B tile 1 while epilogue runs
    float4 pfB[8];
    if (ntiles > 1) {
#pragma unroll
        for (int j = 0; j < 8; j++) {
            int i = tid * 4 + j * 1024;
            int k = i >> 6, n = i & 63;
            pfB[j] = *reinterpret_cast<const float4*>(&W[(size_t)k * ncols + 64 + n]);
        }
    }
    epilogue(0);

    // ================= tile 1 =================
    if (ntiles > 1) {
        __syncthreads();
#pragma unroll
        for (int j = 0; j < 8; j++) {
            int i = tid * 4 + j * 1024;
            int k = i >> 6, n = i & 63;
#pragma unroll
            for (int e = 0; e < 4; e++)
                Bs[b_idx(n + e, k)] = __uint_as_float(f2tf32((&pfB[j].x)[e]));
        }
        __syncthreads();
#pragma unroll
        for (int mi = 0; mi < 2; mi++)
#pragma unroll
            for (int ni = 0; ni < 4; ni++)
#pragma unroll
                for (int j = 0; j < 4; j++) acc[mi][ni][j] = 0.f;
        compute(0, 16);
        epilogue(64);
    }
}

// ---------------- input projection: h = x @ W_in + b_in --------------------
__global__ void input_proj(const float* __restrict__ x,
                           const float* __restrict__ W_in,
                           const float* __restrict__ b_in) {
    int idx = blockIdx.x * blockDim.x + threadIdx.x;
    if (idx >= NN * HH) return;
    int n = idx >> 7, j = idx & 127;
    g_h[idx] = x[n * 2] * W_in[j] + x[n * 2 + 1] * W_in[128 + j] + b_in[j];
}

// ---------------- CSR build (R4-proven 3-phase scan) ------------------------
__global__ void count_kernel(const int* __restrict__ dst) {
    int e = blockIdx.x * blockDim.x + threadIdx.x;
    if (e < EE) atomicAdd(&g_cnt[dst[e]], 1);
}
__global__ void scan1() {
    __shared__ int sm[512];
    int i = blockIdx.x * 512 + threadIdx.x;
    int v = (i < NN) ? g_cnt[i] : 0;
    sm[threadIdx.x] = v;
    __syncthreads();
    for (int off = 1; off < 512; off <<= 1) {
        int t = (threadIdx.x >= off) ? sm[threadIdx.x - off] : 0;
        __syncthreads();
        sm[threadIdx.x] += t;
        __syncthreads();
    }
    if (i < NN) g_incl[i] = sm[threadIdx.x];
    if (threadIdx.x == 511) g_bsum[blockIdx.x] = sm[511];
}
__global__ void scan2(int nch) {
    __shared__ int sm[128];
    int v = (threadIdx.x < nch) ? g_bsum[threadIdx.x] : 0;
    sm[threadIdx.x] = v;
    __syncthreads();
    for (int off = 1; off < 128; off <<= 1) {
        int t = (threadIdx.x >= off) ? sm[threadIdx.x - off] : 0;
        __syncthreads();
        sm[threadIdx.x] += t;
        __syncthreads();
    }
    if (threadIdx.x < nch) g_bofs[threadIdx.x] = sm[threadIdx.x] - v;
}
__global__ void scan3() {
    int i = blockIdx.x * blockDim.x + threadIdx.x;
    if (i < NN) {
        int off = g_incl[i] - g_cnt[i] + g_bofs[i >> 9];
        g_rowoff[i] = off;
        g_cursor[i] = off;
    }
    if (i == 0) g_rowoff[NN] = EE;
}
__global__ void scatter(const int* __restrict__ src, const int* __restrict__ dst) {
    int e = blockIdx.x * blockDim.x + threadIdx.x;
    if (e < EE) {
        int d = dst[e];
        int pos = atomicAdd(&g_cursor[d], 1);
        g_csr[pos] = src[e];
    }
}

__device__ __forceinline__ float lrelu(float t) { return t > 0.f ? t : 0.2f * t; }

// ---------------- ONE-sweep softmax aggregate + bias+relu+res+LN (R8) -------
__global__ void __launch_bounds__(256) aggregate_kernel(
    const float* __restrict__ gb, const float* __restrict__ lng,
    const float* __restrict__ lnb) {
    int n = (blockIdx.x * blockDim.x + threadIdx.x) >> 5;
    if (n >= NN) return;
    int lane = threadIdx.x & 31;
    int beg = g_rowoff[n], end = g_rowoff[n + 1];
    int mh = lane >> 2;
    int c0 = lane * 4;

    float admh = g_ad[n * 8 + mh];
    float asmh = g_as[n * 8 + mh];
    float wself = __expf(lrelu(asmh + admh));
    float den = wself;
    float a0, a1, a2, a3;
    {
        float4 v = *reinterpret_cast<const float4*>(&g_hw[(size_t)n * 128 + c0]);
        a0 = v.x * wself; a1 = v.y * wself; a2 = v.z * wself; a3 = v.w * wself;
    }
    int i = beg;
    for (; i + 2 <= end; i += 2) {
        int s0 = g_csr[i], s1 = g_csr[i + 1];
        float w0 = __expf(lrelu(g_as[s0 * 8 + mh] + admh));
        float w1 = __expf(lrelu(g_as[s1 * 8 + mh] + admh));
        float4 v0 = *reinterpret_cast<const float4*>(&g_hw[(size_t)s0 * 128 + c0]);
        float4 v1 = *reinterpret_cast<const float4*>(&g_hw[(size_t)s1 * 128 + c0]);
        den += w0 + w1;
        a0 = fmaf(v0.x, w0, fmaf(v1.x, w1, a0));
        a1 = fmaf(v0.y, w0, fmaf(v1.y, w1, a1));
        a2 = fmaf(v0.z, w0, fmaf(v1.z, w1, a2));
        a3 = fmaf(v0.w, w0, fmaf(v1.w, w1, a3));
    }
    if (i < end) {
        int s = g_csr[i];
        float wgt = __expf(lrelu(g_as[s * 8 + mh] + admh));
        float4 v = *reinterpret_cast<const float4*>(&g_hw[(size_t)s * 128 + c0]);
        den += wgt;
        a0 = fmaf(v.x, wgt, a0);
        a1 = fmaf(v.y, wgt, a1);
        a2 = fmaf(v.z, wgt, a2);
        a3 = fmaf(v.w, wgt, a3);
    }
    float iv = 1.0f / den;
    float4 b4 = *reinterpret_cast<const float4*>(&gb[c0]);
    float v0 = fmaxf(fmaf(a0, iv, b4.x), 0.f), v1 = fmaxf(fmaf(a1, iv, b4.y), 0.f);
    float v2 = fmaxf(fmaf(a2, iv, b4.z), 0.f), v3 = fmaxf(fmaf(a3, iv, b4.w), 0.f);
    float4 r4 = *reinterpret_cast<const float4*>(&g_h[(size_t)n * 128 + c0]);
    v0 += r4.x; v1 += r4.y; v2 += r4.z; v3 += r4.w;
    float s1 = v0 + v1 + v2 + v3;
    float s2 = v0 * v0 + v1 * v1 + v2 * v2 + v3 * v3;
#pragma unroll
    for (int off = 16; off; off >>= 1) {
        s1 += __shfl_xor_sync(0xffffffffu, s1, off);
        s2 += __shfl_xor_sync(0xffffffffu, s2, off);
    }
    float mu = s1 * (1.f / 128.f);
    float var = s2 * (1.f / 128.f) - mu * mu;
    float rstd = rsqrtf(fmaxf(var, 0.f) + 1e-5f);
    float4 g4 = *reinterpret_cast<const float4*>(&lng[c0]);
    float4 bb4 = *reinterpret_cast<const float4*>(&lnb[c0]);
    float4 o;
    o.x = (v0 - mu) * rstd * g4.x + bb4.x;
    o.y = (v1 - mu) * rstd * g4.y + bb4.y;
    o.z = (v2 - mu) * rstd * g4.z + bb4.z;
    o.w = (v3 - mu) * rstd * g4.w + bb4.w;
    *reinterpret_cast<float4*>(&g_h[(size_t)n * 128 + c0]) = o;
}

// ---------------- launch ----------------------------------------------------
extern "C" void kernel_launch(void* const* d_in, const int* in_sizes, int n_in,
                              void* d_out, int out_size) {
    const float* x = (const float*)d_in[0];
    const int* ei = (const int*)d_in[1];
    const int* src = ei;
    const int* dst = ei + EE;
    const float* W_in = (const float*)d_in[3];
    const float* b_in = (const float*)d_in[4];
    float* out = (float*)d_out;

    float *p_h = nullptr, *p_hw = nullptr;
    int* p_cnt = nullptr;
    cudaGetSymbolAddress((void**)&p_h, g_h);
    cudaGetSymbolAddress((void**)&p_hw, g_hw);
    cudaGetSymbolAddress((void**)&p_cnt, g_cnt);

    const int SMEM_GEMM = (16384 + 8192) * 4;  // 96 KB
    cudaFuncSetAttribute(mma_gemm<0>, cudaFuncAttributeMaxDynamicSharedMemorySize, SMEM_GEMM);
    cudaFuncSetAttribute(mma_gemm<1>, cudaFuncAttributeMaxDynamicSharedMemorySize, SMEM_GEMM);
    cudaFuncSetAttribute(mma_gemm<2>, cudaFuncAttributeMaxDynamicSharedMemorySize, SMEM_GEMM);
    const int NCTA = (NN + 127) / 128;  // 391

    input_proj<<<(NN * HH + 255) / 256, 256>>>(x, W_in, b_in);

    cudaMemsetAsync(p_cnt, 0, NN * sizeof(int));
    count_kernel<<<(EE + 255) / 256, 256>>>(dst);
    scan1<<<(NN + 511) / 512, 512>>>();
    scan2<<<1, 128>>>((NN + 511) / 512);
    scan3<<<(NN + 255) / 256, 256>>>();
    scatter<<<(EE + 255) / 256, 256>>>(src, dst);

    for (int l = 0; l < 3; l++) {
        const float* W  = (const float*)d_in[5 + 6 * l];
        const float* as = (const float*)d_in[6 + 6 * l];
        const float* ad = (const float*)d_in[7 + 6 * l];
        const float* gb = (const float*)d_in[8 + 6 * l];
        const float* lg = (const float*)d_in[9 + 6 * l];
        const float* lb = (const float*)d_in[10 + 6 * l];
        mma_gemm<0><<<NCTA, 256, SMEM_GEMM>>>(p_h, W, 128, as, ad, p_hw, NN, nullptr, nullptr);
        aggregate_kernel<<<(NN + 7) / 8, 256>>>(gb, lg, lb);
    }
    // MLP head: h1 = relu(h@W1+b1) -> g_hw ; out = relu(h1@W2+b2)@W3 + b3 (fused)
    mma_gemm<1><<<NCTA, 256, SMEM_GEMM>>>(p_h, (const float*)d_in[23], 128,
                                          (const float*)d_in[24], nullptr, p_hw, NN,
                                          nullptr, nullptr);
    mma_gemm<2><<<NCTA, 256, SMEM_GEMM>>>(p_hw, (const float*)d_in[25], 64,
                                          (const float*)d_in[26], (const float*)d_in[27],
                                          nullptr, NN, (const float*)d_in[28], out);
}